// round 6
// baseline (speedup 1.0000x reference)
#include <cuda_runtime.h>
#include <cstdint>

// ---------------- scratch (device globals; no allocation allowed) -------------
#define MAXN 50000
#define MAXE 500000

__device__ float g_xl[MAXN * 128];
__device__ float g_xr[MAXN * 128];
__device__ float g_xcat[MAXN * 512];
__device__ float g_elog[MAXE * 16];
__device__ float g_nmax[MAXN * 16];
__device__ float g_nsum[MAXN * 16];
__device__ float g_WTA[128 * 128];
__device__ float g_WTB[128 * 128];
__device__ float g_WeT[128 * 128];
__device__ float g_fuseT[128 * 512];
__device__ float g_mlpT[128 * 256];

// ---------------- helpers -----------------------------------------------------

__device__ __forceinline__ void atomicMaxF(float* addr, float v) {
    if (v >= 0.f) atomicMax((int*)addr, __float_as_int(v));
    else          atomicMin((unsigned int*)addr, __float_as_uint(v));
}

// W: [K,128] row-major  ->  WT: [128,K]
__global__ void transposeW(const float* __restrict__ W, float* __restrict__ WT, int K) {
    int idx = blockIdx.x * blockDim.x + threadIdx.x;
    if (idx < K * 128) {
        int k = idx >> 7, c = idx & 127;
        WT[c * K + k] = W[idx];
    }
}

// out[M,128] = A[M,K] @ W[K,128] (+bias), W given transposed as WT[128,K].
// 128 threads/block, 8 rows/block.
template <int K>
__global__ void gemm128(const float* __restrict__ A, const float* __restrict__ WT,
                        const float* __restrict__ bias, float* __restrict__ out, int M) {
    __shared__ float As[8 * K];
    const int t = threadIdx.x;
    const int r0 = blockIdx.x * 8;

    // stage 8 rows of A (zero-fill out-of-range rows)
    for (int i = t * 4; i < 8 * K; i += 128 * 4) {
        int gr = r0 + i / K;
        float4 v = (gr < M) ? *(const float4*)&A[(size_t)r0 * K + i]
                            : make_float4(0.f, 0.f, 0.f, 0.f);
        *(float4*)&As[i] = v;
    }
    __syncthreads();

    float b = bias ? bias[t] : 0.f;
    float acc[8];
#pragma unroll
    for (int r = 0; r < 8; r++) acc[r] = b;

    const float* wt = &WT[t * K];
#pragma unroll 4
    for (int k = 0; k < K; k += 4) {
        float4 w = *(const float4*)&wt[k];
#pragma unroll
        for (int r = 0; r < 8; r++) {
            float4 a = *(const float4*)&As[r * K + k];
            acc[r] += a.x * w.x + a.y * w.y + a.z * w.z + a.w * w.w;
        }
    }
#pragma unroll
    for (int r = 0; r < 8; r++) {
        int row = r0 + r;
        if (row < M) out[(size_t)row * 128 + t] = acc[r];
    }
}

// xcat[n, c*128+j] = b_c[j]  (bias init of the concatenated conv outputs)
__global__ void init_xcat(float* __restrict__ xcat,
                          const float* __restrict__ b1, const float* __restrict__ b2,
                          const float* __restrict__ b3, const float* __restrict__ b4, int N) {
    int idx = blockIdx.x * blockDim.x + threadIdx.x;
    if (idx >= N * 512) return;
    int col = idx & 511;
    int c = col >> 7, j = col & 127;
    const float* b = (c == 0) ? b1 : (c == 1) ? b2 : (c == 2) ? b3 : b4;
    xcat[idx] = b[j];
}

__global__ void init_ns(float* __restrict__ nmax, float* __restrict__ nsum, int n) {
    int idx = blockIdx.x * blockDim.x + threadIdx.x;
    if (idx < n) {
        nmax[idx] = __int_as_float(0xff800000);  // -inf
        nsum[idx] = 0.f;
    }
}

// Pass A: per-edge logits (+ optional inline eattr@We), atomicMax into nmax.
// 256 threads = 2 edge slots of 128 threads.
template <bool HASE>
__global__ void edge_logits(const int* __restrict__ src, const int* __restrict__ dst, int E,
                            const float* __restrict__ xl, const float* __restrict__ xr,
                            const float* __restrict__ eattr, const float* __restrict__ WeT,
                            const float* __restrict__ att, float* __restrict__ elog,
                            float* __restrict__ nmax) {
    __shared__ float es[2][128];
    const int slot = threadIdx.x >> 7;
    const int t = threadIdx.x & 127;
    const int e = blockIdx.x * 2 + slot;
    const bool valid = (e < E);

    int s = 0, d = 0;
    float m = 0.f;
    if (valid) {
        s = src[e]; d = dst[e];
        m = xl[(size_t)s * 128 + t] + xr[(size_t)d * 128 + t];
    }
    if (HASE) {
        es[slot][t] = valid ? eattr[(size_t)e * 128 + t] : 0.f;
        __syncthreads();
        float acc = 0.f;
        const float* wt = &WeT[t * 128];
#pragma unroll 8
        for (int k = 0; k < 128; k += 4) {
            float4 a = *(const float4*)&es[slot][k];
            float4 w = *(const float4*)&wt[k];
            acc += a.x * w.x + a.y * w.y + a.z * w.z + a.w * w.w;
        }
        m += acc;
    }
    float lm = (m > 0.f) ? m : 0.2f * m;          // leaky_relu slope 0.2
    float partial = lm * att[t];
    // reduce over C=8 lanes (aligned groups of 8 within a warp)
#pragma unroll
    for (int off = 4; off; off >>= 1)
        partial += __shfl_xor_sync(0xffffffffu, partial, off);

    if (valid && (t & 7) == 0) {
        int h = t >> 3;
        elog[(size_t)e * 16 + h] = partial;
        atomicMaxF(&nmax[(size_t)d * 16 + h], partial);
    }
}

// Pass B: e = exp(logit - max[dst]); accumulate segment sums.
__global__ void edge_exp(const int* __restrict__ dst, int E,
                         const float* __restrict__ nmax, float* __restrict__ elog,
                         float* __restrict__ nsum) {
    int idx = blockIdx.x * blockDim.x + threadIdx.x;
    if (idx >= E * 16) return;
    int e = idx >> 4, h = idx & 15;
    int d = dst[e];
    float v = __expf(elog[idx] - nmax[(size_t)d * 16 + h]);
    elog[idx] = v;
    atomicAdd(&nsum[(size_t)d * 16 + h], v);
}

// Pass C: alpha-weighted scatter of xl[src] into xcat[dst] (vector RED).
// 32 threads per edge, 8 edges per 256-thread block.
__global__ void edge_agg(const int* __restrict__ src, const int* __restrict__ dst, int E,
                         const float* __restrict__ elog, const float* __restrict__ nsum,
                         const float* __restrict__ xl, float* __restrict__ xcat, int cofs) {
    const int l = threadIdx.x & 31;
    const int slot = threadIdx.x >> 5;
    const int e = blockIdx.x * 8 + slot;
    if (e >= E) return;
    int s = src[e], d = dst[e];
    int h = l >> 1;
    float alpha = elog[(size_t)e * 16 + h] / (nsum[(size_t)d * 16 + h] + 1e-16f);
    float4 v = *(const float4*)&xl[(size_t)s * 128 + l * 4];
    float* p = &xcat[(size_t)d * 512 + cofs + l * 4];
    asm volatile("red.global.add.v4.f32 [%0], {%1,%2,%3,%4};" ::
                 "l"(p), "f"(alpha * v.x), "f"(alpha * v.y),
                 "f"(alpha * v.z), "f"(alpha * v.w) : "memory");
}

// Per-edge: pair = [xf[src], xf[dst]] -> LN -> relu -> @mlp_W + mlp_b + edge_attr
// 128 threads per block, one edge per block.
__global__ void edge_mlp(const int* __restrict__ src, const int* __restrict__ dst,
                         const float* __restrict__ xf,
                         const float* __restrict__ lng, const float* __restrict__ lnb,
                         const float* __restrict__ mlpT, const float* __restrict__ mlpb,
                         const float* __restrict__ eattr, float* __restrict__ out) {
    __shared__ float ps[256];
    __shared__ float red[8];
    __shared__ float s_mu, s_rs;
    const int t = threadIdx.x;
    const int e = blockIdx.x;
    int s = src[e], d = dst[e];
    float a = xf[(size_t)s * 128 + t];
    float b = xf[(size_t)d * 128 + t];
    ps[t] = a; ps[128 + t] = b;

    float sum = a + b, sq = a * a + b * b;
#pragma unroll
    for (int off = 16; off; off >>= 1) {
        sum += __shfl_xor_sync(0xffffffffu, sum, off);
        sq  += __shfl_xor_sync(0xffffffffu, sq, off);
    }
    int w = t >> 5;
    if ((t & 31) == 0) { red[w] = sum; red[4 + w] = sq; }
    __syncthreads();
    if (t == 0) {
        float S = red[0] + red[1] + red[2] + red[3];
        float Q = red[4] + red[5] + red[6] + red[7];
        float mu = S * (1.f / 256.f);
        float var = Q * (1.f / 256.f) - mu * mu;
        s_mu = mu;
        s_rs = rsqrtf(var + 1e-5f);
    }
    __syncthreads();
    float mu = s_mu, rs = s_rs;
    float r0 = fmaxf(0.f, (ps[t] - mu) * rs * lng[t] + lnb[t]);
    float r1 = fmaxf(0.f, (ps[128 + t] - mu) * rs * lng[128 + t] + lnb[128 + t]);
    __syncthreads();
    ps[t] = r0; ps[128 + t] = r1;
    __syncthreads();

    float acc = mlpb[t];
    const float* wt = &mlpT[t * 256];
#pragma unroll 8
    for (int k = 0; k < 256; k += 4) {
        float4 rr = *(const float4*)&ps[k];
        float4 w4 = *(const float4*)&wt[k];
        acc += rr.x * w4.x + rr.y * w4.y + rr.z * w4.z + rr.w * w4.w;
    }
    out[(size_t)e * 128 + t] = eattr[(size_t)e * 128 + t] + acc;
}

// dual_out[i] = (idx==E) ? ones : edge_attr_new[idx]
__global__ void dual_gather(const int* __restrict__ idx, int M, int E,
                            const float* __restrict__ ea, float* __restrict__ out) {
    int tid = blockIdx.x * blockDim.x + threadIdx.x;
    if (tid >= M * 32) return;
    int i = tid >> 5, l = tid & 31;
    int id = idx[i];
    float4 v;
    if (id >= E) v = make_float4(1.f, 1.f, 1.f, 1.f);
    else         v = *(const float4*)&ea[(size_t)id * 128 + l * 4];
    *(float4*)&out[(size_t)i * 128 + l * 4] = v;
}

// ---------------- host orchestration ------------------------------------------

extern "C" void kernel_launch(void* const* d_in, const int* in_sizes, int n_in,
                              void* d_out, int out_size) {
    const float* x         = (const float*)d_in[0];
    const int*   ei[4]     = {(const int*)d_in[1], (const int*)d_in[2],
                              (const int*)d_in[3], (const int*)d_in[4]};
    const float* dual_attr = (const float*)d_in[5];
    const float* edge_attr = (const float*)d_in[6];
    const int*   oemap     = (const int*)d_in[7];

    const float *Wl[4], *Wr[4], *att[4], *bb[4];
    int p = 8;
    for (int c = 0; c < 4; c++) {
        Wl[c]  = (const float*)d_in[p++];
        Wr[c]  = (const float*)d_in[p++];
        att[c] = (const float*)d_in[p++];
        bb[c]  = (const float*)d_in[p++];
    }
    const float* We1    = (const float*)d_in[24];
    const float* fuse_W = (const float*)d_in[25];
    const float* fuse_b = (const float*)d_in[26];
    const float* ln_g   = (const float*)d_in[27];
    const float* ln_b   = (const float*)d_in[28];
    const float* mlp_W  = (const float*)d_in[29];
    const float* mlp_b  = (const float*)d_in[30];

    const int N    = in_sizes[0] / 128;
    const int Ec[4] = {in_sizes[1] / 2, in_sizes[2] / 2, in_sizes[3] / 2, in_sizes[4] / 2};
    const int M_oe = in_sizes[7];
    const int E1   = Ec[0];

    float *xl, *xr, *xcat, *elog, *nmax, *nsum, *WTA, *WTB, *WeT, *fuseT, *mlpT;
    cudaGetSymbolAddress((void**)&xl,    g_xl);
    cudaGetSymbolAddress((void**)&xr,    g_xr);
    cudaGetSymbolAddress((void**)&xcat,  g_xcat);
    cudaGetSymbolAddress((void**)&elog,  g_elog);
    cudaGetSymbolAddress((void**)&nmax,  g_nmax);
    cudaGetSymbolAddress((void**)&nsum,  g_nsum);
    cudaGetSymbolAddress((void**)&WTA,   g_WTA);
    cudaGetSymbolAddress((void**)&WTB,   g_WTB);
    cudaGetSymbolAddress((void**)&WeT,   g_WeT);
    cudaGetSymbolAddress((void**)&fuseT, g_fuseT);
    cudaGetSymbolAddress((void**)&mlpT,  g_mlpT);

    // one-time weight transposes (per call; cheap)
    transposeW<<<(128 * 128 + 255) / 256, 256>>>(We1, WeT, 128);
    transposeW<<<(512 * 128 + 255) / 256, 256>>>(fuse_W, fuseT, 512);
    transposeW<<<(256 * 128 + 255) / 256, 256>>>(mlp_W, mlpT, 256);

    init_xcat<<<(N * 512 + 255) / 256, 256>>>(xcat, bb[0], bb[1], bb[2], bb[3], N);

    for (int c = 0; c < 4; c++) {
        const int E = Ec[c];
        const int* src = ei[c];
        const int* dst = ei[c] + E;

        transposeW<<<(128 * 128 + 255) / 256, 256>>>(Wl[c], WTA, 128);
        transposeW<<<(128 * 128 + 255) / 256, 256>>>(Wr[c], WTB, 128);
        gemm128<128><<<(N + 7) / 8, 128>>>(x, WTA, nullptr, xl, N);
        gemm128<128><<<(N + 7) / 8, 128>>>(x, WTB, nullptr, xr, N);
        init_ns<<<(N * 16 + 255) / 256, 256>>>(nmax, nsum, N * 16);

        if (c == 0)
            edge_logits<true><<<(E + 1) / 2, 256>>>(src, dst, E, xl, xr,
                                                    dual_attr, WeT, att[c], elog, nmax);
        else
            edge_logits<false><<<(E + 1) / 2, 256>>>(src, dst, E, xl, xr,
                                                     nullptr, nullptr, att[c], elog, nmax);

        edge_exp<<<(E * 16 + 255) / 256, 256>>>(dst, E, nmax, elog, nsum);
        edge_agg<<<(E + 7) / 8, 256>>>(src, dst, E, elog, nsum, xl, xcat, c * 128);
    }

    // fuse: xf = xcat @ fuse_W + fuse_b  -> output section 0
    float* xf = (float*)d_out;
    gemm128<512><<<(N + 7) / 8, 128>>>(xcat, fuseT, fuse_b, xf, N);

    // edge MLP -> output section 1
    float* eout = (float*)d_out + (size_t)N * 128;
    edge_mlp<<<E1, 128>>>(ei[0], ei[0] + E1, xf, ln_g, ln_b, mlpT, mlp_b, edge_attr, eout);

    // dual gather -> output section 2
    float* dout = eout + (size_t)E1 * 128;
    dual_gather<<<(M_oe * 32 + 255) / 256, 256>>>(oemap, M_oe, E1, eout, dout);
}

// round 7
// speedup vs baseline: 5.4176x; 5.4176x over previous
#include <cuda_runtime.h>
#include <cstdint>

// ---------------- scratch (device globals; no allocation allowed) -------------
#define MAXN 50000
#define MAXE 500000

__device__ float g_xl[MAXN * 128];
__device__ float g_xr[MAXN * 128];
__device__ float g_xcat[MAXN * 512];
__device__ float g_elog[MAXE * 16];
__device__ float g_nmax[MAXN * 16];
__device__ float g_nsum[MAXN * 16];
__device__ float g_pre[(size_t)MAXE * 128];   // dual_attr @ We1

// ---------------- helpers -----------------------------------------------------

__device__ __forceinline__ void atomicMaxF(float* addr, float v) {
    if (v >= 0.f) atomicMax((int*)addr, __float_as_int(v));
    else          atomicMin((unsigned int*)addr, __float_as_uint(v));
}

// ---------------- tiled GEMM: out[M,128] = A[M,K] @ W[K,128] (+bias) ----------
// 256 threads, 32 rows per block, K in tiles of 128. Dynamic smem: 80 KB.
template <int K>
__global__ void gemm_t(const float* __restrict__ A, const float* __restrict__ W,
                       const float* __restrict__ bias, float* __restrict__ out, int M) {
    extern __shared__ float sm[];
    float* As = sm;             // 32 * 128
    float* Ws = sm + 32 * 128;  // 128 * 128

    const int tid = threadIdx.x;
    const int tx = tid & 31;        // col group: cols tx*4..tx*4+3
    const int ty = tid >> 5;        // row group: rows ty*4..ty*4+3
    const int r0 = blockIdx.x * 32;

    float4 acc[4];
    float4 binit = bias ? *(const float4*)&bias[tx * 4] : make_float4(0.f, 0.f, 0.f, 0.f);
#pragma unroll
    for (int i = 0; i < 4; i++) acc[i] = binit;

    for (int kt = 0; kt < K; kt += 128) {
        // stage A[32, kt:kt+128]
#pragma unroll
        for (int i = tid; i < 32 * 32; i += 256) {
            int r = i >> 5, c4 = i & 31;
            float4 v = (r0 + r < M)
                ? *(const float4*)&A[(size_t)(r0 + r) * K + kt + c4 * 4]
                : make_float4(0.f, 0.f, 0.f, 0.f);
            *(float4*)&As[r * 128 + c4 * 4] = v;
        }
        // stage W[kt:kt+128, 0:128]
#pragma unroll
        for (int i = tid; i < 128 * 32; i += 256) {
            int k = i >> 5, c4 = i & 31;
            *(float4*)&Ws[k * 128 + c4 * 4] =
                *(const float4*)&W[(size_t)(kt + k) * 128 + c4 * 4];
        }
        __syncthreads();

#pragma unroll 4
        for (int k = 0; k < 128; k++) {
            float4 w4 = *(const float4*)&Ws[k * 128 + tx * 4];
#pragma unroll
            for (int i = 0; i < 4; i++) {
                float a = As[(ty * 4 + i) * 128 + k];
                acc[i].x += a * w4.x; acc[i].y += a * w4.y;
                acc[i].z += a * w4.z; acc[i].w += a * w4.w;
            }
        }
        __syncthreads();
    }

#pragma unroll
    for (int i = 0; i < 4; i++) {
        int r = r0 + ty * 4 + i;
        if (r < M) *(float4*)&out[(size_t)r * 128 + tx * 4] = acc[i];
    }
}

// xcat[n, c*128+j] = b_c[j]  (bias init of the concatenated conv outputs), float4
__global__ void init_xcat(float* __restrict__ xcat,
                          const float* __restrict__ b1, const float* __restrict__ b2,
                          const float* __restrict__ b3, const float* __restrict__ b4, int N) {
    int idx = blockIdx.x * blockDim.x + threadIdx.x;
    if (idx >= N * 128) return;
    int col4 = idx & 127;
    int c = col4 >> 5, j4 = col4 & 31;
    const float* b = (c == 0) ? b1 : (c == 1) ? b2 : (c == 2) ? b3 : b4;
    *(float4*)&xcat[(size_t)idx * 4] = *(const float4*)&b[j4 * 4];
}

__global__ void init_ns(float* __restrict__ nmax, float* __restrict__ nsum, int n) {
    int idx = blockIdx.x * blockDim.x + threadIdx.x;
    if (idx < n) {
        nmax[idx] = __int_as_float(0xff800000);  // -inf
        nsum[idx] = 0.f;
    }
}

// Pass A: per-edge logits; 32 threads (1 warp) per edge, 8 edges / 256-thread block.
template <bool HASE>
__global__ void edge_logits(const int* __restrict__ src, const int* __restrict__ dst, int E,
                            const float* __restrict__ xl, const float* __restrict__ xr,
                            const float* __restrict__ pre,
                            const float* __restrict__ att, float* __restrict__ elog,
                            float* __restrict__ nmax) {
    const int l = threadIdx.x & 31;
    const int slot = threadIdx.x >> 5;
    const int e = blockIdx.x * 8 + slot;
    if (e >= E) return;
    int s = src[e], d = dst[e];
    float4 a = *(const float4*)&xl[(size_t)s * 128 + l * 4];
    float4 b = *(const float4*)&xr[(size_t)d * 128 + l * 4];
    float4 m = make_float4(a.x + b.x, a.y + b.y, a.z + b.z, a.w + b.w);
    if (HASE) {
        float4 p = *(const float4*)&pre[(size_t)e * 128 + l * 4];
        m.x += p.x; m.y += p.y; m.z += p.z; m.w += p.w;
    }
    float4 t4 = *(const float4*)&att[l * 4];
    float lx = (m.x > 0.f) ? m.x : 0.2f * m.x;
    float ly = (m.y > 0.f) ? m.y : 0.2f * m.y;
    float lz = (m.z > 0.f) ? m.z : 0.2f * m.z;
    float lw = (m.w > 0.f) ? m.w : 0.2f * m.w;
    float partial = lx * t4.x + ly * t4.y + lz * t4.z + lw * t4.w;
    partial += __shfl_xor_sync(0xffffffffu, partial, 1);   // 2 lanes per head

    if ((l & 1) == 0) {
        int h = l >> 1;
        elog[(size_t)e * 16 + h] = partial;
        atomicMaxF(&nmax[(size_t)d * 16 + h], partial);
    }
}

// Pass B: e = exp(logit - max[dst]); accumulate segment sums.
__global__ void edge_exp(const int* __restrict__ dst, int E,
                         const float* __restrict__ nmax, float* __restrict__ elog,
                         float* __restrict__ nsum) {
    int idx = blockIdx.x * blockDim.x + threadIdx.x;
    if (idx >= E * 16) return;
    int e = idx >> 4, h = idx & 15;
    int d = dst[e];
    float v = __expf(elog[idx] - nmax[(size_t)d * 16 + h]);
    elog[idx] = v;
    atomicAdd(&nsum[(size_t)d * 16 + h], v);
}

// Pass C: alpha-weighted scatter of xl[src] into xcat[dst] (vector RED).
__global__ void edge_agg(const int* __restrict__ src, const int* __restrict__ dst, int E,
                         const float* __restrict__ elog, const float* __restrict__ nsum,
                         const float* __restrict__ xl, float* __restrict__ xcat, int cofs) {
    const int l = threadIdx.x & 31;
    const int slot = threadIdx.x >> 5;
    const int e = blockIdx.x * 8 + slot;
    if (e >= E) return;
    int s = src[e], d = dst[e];
    int h = l >> 1;
    float alpha = elog[(size_t)e * 16 + h] / (nsum[(size_t)d * 16 + h] + 1e-16f);
    float4 v = *(const float4*)&xl[(size_t)s * 128 + l * 4];
    float* p = &xcat[(size_t)d * 512 + cofs + l * 4];
    asm volatile("red.global.add.v4.f32 [%0], {%1,%2,%3,%4};" ::
                 "l"(p), "f"(alpha * v.x), "f"(alpha * v.y),
                 "f"(alpha * v.z), "f"(alpha * v.w) : "memory");
}

// ---------------- persistent edge MLP -----------------------------------------
// 512 threads, mlp_W fully cached in smem (128 KB). Each warp owns 4 edges per
// batch: LN+relu into warp-private ps rows, then matvec reusing each W LDS.128
// across 4 edges x 4 outputs. No block sync in the mainloop.
__global__ __launch_bounds__(512, 1)
void edge_mlp(const int* __restrict__ src, const int* __restrict__ dst, int E,
              const float* __restrict__ xf,
              const float* __restrict__ lng, const float* __restrict__ lnb,
              const float* __restrict__ W, const float* __restrict__ mlpb,
              const float* __restrict__ eattr, float* __restrict__ out) {
    extern __shared__ float sm[];
    float* Ws = sm;                 // 256*128 = 32768
    float* ps = sm + 32768;         // 64 edges * 256
    float* lg = ps + 64 * 256;      // 256
    float* lb = lg + 256;           // 256
    float* mb = lb + 256;           // 128

    const int tid = threadIdx.x;
    const int l = tid & 31;
    const int w = tid >> 5;         // warp 0..15

    // stage weights + consts (coalesced)
#pragma unroll
    for (int i = tid; i < 8192; i += 512)
        *(float4*)&Ws[i * 4] = *(const float4*)&W[(size_t)i * 4];
    if (tid < 256) { lg[tid] = lng[tid]; lb[tid] = lnb[tid]; }
    if (tid < 128) mb[tid] = mlpb[tid];
    __syncthreads();

    float* psw = &ps[(w * 4) * 256];   // warp-private 4 rows

    for (int base = blockIdx.x * 64; base < E; base += gridDim.x * 64) {
        // ---- LN + relu into ps (warp-local) ----
#pragma unroll
        for (int e = 0; e < 4; e++) {
            int ge = base + w * 4 + e;
            float4 ra, rb;
            if (ge < E) {
                int s = src[ge], d = dst[ge];
                float4 a = *(const float4*)&xf[(size_t)s * 128 + l * 4];
                float4 b = *(const float4*)&xf[(size_t)d * 128 + l * 4];
                float sum = a.x + a.y + a.z + a.w + b.x + b.y + b.z + b.w;
                float sq  = a.x * a.x + a.y * a.y + a.z * a.z + a.w * a.w
                          + b.x * b.x + b.y * b.y + b.z * b.z + b.w * b.w;
#pragma unroll
                for (int off = 16; off; off >>= 1) {
                    sum += __shfl_xor_sync(0xffffffffu, sum, off);
                    sq  += __shfl_xor_sync(0xffffffffu, sq, off);
                }
                float mu = sum * (1.f / 256.f);
                float var = sq * (1.f / 256.f) - mu * mu;
                float rs = rsqrtf(var + 1e-5f);
                float4 ga = *(const float4*)&lg[l * 4];
                float4 ba = *(const float4*)&lb[l * 4];
                float4 gb = *(const float4*)&lg[128 + l * 4];
                float4 bb = *(const float4*)&lb[128 + l * 4];
                ra.x = fmaxf(0.f, (a.x - mu) * rs * ga.x + ba.x);
                ra.y = fmaxf(0.f, (a.y - mu) * rs * ga.y + ba.y);
                ra.z = fmaxf(0.f, (a.z - mu) * rs * ga.z + ba.z);
                ra.w = fmaxf(0.f, (a.w - mu) * rs * ga.w + ba.w);
                rb.x = fmaxf(0.f, (b.x - mu) * rs * gb.x + bb.x);
                rb.y = fmaxf(0.f, (b.y - mu) * rs * gb.y + bb.y);
                rb.z = fmaxf(0.f, (b.z - mu) * rs * gb.z + bb.z);
                rb.w = fmaxf(0.f, (b.w - mu) * rs * gb.w + bb.w);
            } else {
                ra = rb = make_float4(0.f, 0.f, 0.f, 0.f);
            }
            *(float4*)&psw[e * 256 + l * 4]       = ra;
            *(float4*)&psw[e * 256 + 128 + l * 4] = rb;
        }
        __syncwarp();

        // ---- matvec: 4 edges x 4 output cols per lane ----
        float4 acc0, acc1, acc2, acc3;
        float4 binit = *(const float4*)&mb[l * 4];
        acc0 = acc1 = acc2 = acc3 = binit;

#pragma unroll 2
        for (int k = 0; k < 256; k += 4) {
            float4 p0 = *(const float4*)&psw[0 * 256 + k];
            float4 p1 = *(const float4*)&psw[1 * 256 + k];
            float4 p2 = *(const float4*)&psw[2 * 256 + k];
            float4 p3 = *(const float4*)&psw[3 * 256 + k];
            const float* pp0 = &p0.x;
            const float* pp1 = &p1.x;
            const float* pp2 = &p2.x;
            const float* pp3 = &p3.x;
#pragma unroll
            for (int kk = 0; kk < 4; kk++) {
                float4 w4 = *(const float4*)&Ws[(k + kk) * 128 + l * 4];
                float q0 = pp0[kk], q1 = pp1[kk], q2 = pp2[kk], q3 = pp3[kk];
                acc0.x += q0 * w4.x; acc0.y += q0 * w4.y; acc0.z += q0 * w4.z; acc0.w += q0 * w4.w;
                acc1.x += q1 * w4.x; acc1.y += q1 * w4.y; acc1.z += q1 * w4.z; acc1.w += q1 * w4.w;
                acc2.x += q2 * w4.x; acc2.y += q2 * w4.y; acc2.z += q2 * w4.z; acc2.w += q2 * w4.w;
                acc3.x += q3 * w4.x; acc3.y += q3 * w4.y; acc3.z += q3 * w4.z; acc3.w += q3 * w4.w;
            }
        }

        // ---- epilogue: + edge_attr, store ----
        float4 accs[4] = {acc0, acc1, acc2, acc3};
#pragma unroll
        for (int e = 0; e < 4; e++) {
            int ge = base + w * 4 + e;
            if (ge >= E) continue;
            float4 ea = *(const float4*)&eattr[(size_t)ge * 128 + l * 4];
            float4 o = make_float4(ea.x + accs[e].x, ea.y + accs[e].y,
                                   ea.z + accs[e].z, ea.w + accs[e].w);
            *(float4*)&out[(size_t)ge * 128 + l * 4] = o;
        }
    }
}

// dual_out[i] = (idx==E) ? ones : edge_attr_new[idx]
__global__ void dual_gather(const int* __restrict__ idx, int M, int E,
                            const float* __restrict__ ea, float* __restrict__ out) {
    int tid = blockIdx.x * blockDim.x + threadIdx.x;
    if (tid >= M * 32) return;
    int i = tid >> 5, l = tid & 31;
    int id = idx[i];
    float4 v;
    if (id >= E) v = make_float4(1.f, 1.f, 1.f, 1.f);
    else         v = *(const float4*)&ea[(size_t)id * 128 + l * 4];
    *(float4*)&out[(size_t)i * 128 + l * 4] = v;
}

// ---------------- host orchestration ------------------------------------------

static const int GEMM_SMEM = (32 * 128 + 128 * 128) * 4;                 // 80 KB
static const int MLP_SMEM  = (32768 + 64 * 256 + 256 + 256 + 128) * 4;   // ~195 KB

extern "C" void kernel_launch(void* const* d_in, const int* in_sizes, int n_in,
                              void* d_out, int out_size) {
    const float* x         = (const float*)d_in[0];
    const int*   ei[4]     = {(const int*)d_in[1], (const int*)d_in[2],
                              (const int*)d_in[3], (const int*)d_in[4]};
    const float* dual_attr = (const float*)d_in[5];
    const float* edge_attr = (const float*)d_in[6];
    const int*   oemap     = (const int*)d_in[7];

    const float *Wl[4], *Wr[4], *att[4], *bb[4];
    int p = 8;
    for (int c = 0; c < 4; c++) {
        Wl[c]  = (const float*)d_in[p++];
        Wr[c]  = (const float*)d_in[p++];
        att[c] = (const float*)d_in[p++];
        bb[c]  = (const float*)d_in[p++];
    }
    const float* We1    = (const float*)d_in[24];
    const float* fuse_W = (const float*)d_in[25];
    const float* fuse_b = (const float*)d_in[26];
    const float* ln_g   = (const float*)d_in[27];
    const float* ln_b   = (const float*)d_in[28];
    const float* mlp_W  = (const float*)d_in[29];
    const float* mlp_b  = (const float*)d_in[30];

    const int N     = in_sizes[0] / 128;
    const int Ec[4] = {in_sizes[1] / 2, in_sizes[2] / 2, in_sizes[3] / 2, in_sizes[4] / 2};
    const int M_oe  = in_sizes[7];
    const int E1    = Ec[0];

    float *xl, *xr, *xcat, *elog, *nmax, *nsum, *pre;
    cudaGetSymbolAddress((void**)&xl,   g_xl);
    cudaGetSymbolAddress((void**)&xr,   g_xr);
    cudaGetSymbolAddress((void**)&xcat, g_xcat);
    cudaGetSymbolAddress((void**)&elog, g_elog);
    cudaGetSymbolAddress((void**)&nmax, g_nmax);
    cudaGetSymbolAddress((void**)&nsum, g_nsum);
    cudaGetSymbolAddress((void**)&pre,  g_pre);

    // opt-in large dynamic smem (idempotent; host-side, capture-safe)
    cudaFuncSetAttribute(gemm_t<128>, cudaFuncAttributeMaxDynamicSharedMemorySize, GEMM_SMEM);
    cudaFuncSetAttribute(gemm_t<512>, cudaFuncAttributeMaxDynamicSharedMemorySize, GEMM_SMEM);
    cudaFuncSetAttribute(edge_mlp,    cudaFuncAttributeMaxDynamicSharedMemorySize, MLP_SMEM);

    // pre = dual_attr @ We1 (removes per-edge matvec from edge_logits)
    gemm_t<128><<<(E1 + 31) / 32, 256, GEMM_SMEM>>>(dual_attr, We1, nullptr, pre, E1);

    init_xcat<<<(N * 128 + 255) / 256, 256>>>(xcat, bb[0], bb[1], bb[2], bb[3], N);

    for (int c = 0; c < 4; c++) {
        const int E = Ec[c];
        const int* src = ei[c];
        const int* dst = ei[c] + E;

        gemm_t<128><<<(N + 31) / 32, 256, GEMM_SMEM>>>(x, Wl[c], nullptr, xl, N);
        gemm_t<128><<<(N + 31) / 32, 256, GEMM_SMEM>>>(x, Wr[c], nullptr, xr, N);
        init_ns<<<(N * 16 + 255) / 256, 256>>>(nmax, nsum, N * 16);

        if (c == 0)
            edge_logits<true><<<(E + 7) / 8, 256>>>(src, dst, E, xl, xr, pre,
                                                    att[c], elog, nmax);
        else
            edge_logits<false><<<(E + 7) / 8, 256>>>(src, dst, E, xl, xr, nullptr,
                                                     att[c], elog, nmax);

        edge_exp<<<(E * 16 + 255) / 256, 256>>>(dst, E, nmax, elog, nsum);
        edge_agg<<<(E + 7) / 8, 256>>>(src, dst, E, elog, nsum, xl, xcat, c * 128);
    }

    // fuse: xf = xcat @ fuse_W + fuse_b  -> output section 0
    float* xf = (float*)d_out;
    gemm_t<512><<<(N + 31) / 32, 256, GEMM_SMEM>>>(xcat, fuse_W, fuse_b, xf, N);

    // edge MLP -> output section 1 (persistent, W cached in smem)
    float* eout = (float*)d_out + (size_t)N * 128;
    edge_mlp<<<152, 512, MLP_SMEM>>>(ei[0], ei[0] + E1, E1, xf, ln_g, ln_b,
                                     mlp_W, mlp_b, edge_attr, eout);

    // dual gather -> output section 2
    float* dout = eout + (size_t)E1 * 128;
    dual_gather<<<(M_oe * 32 + 255) / 256, 256>>>(oemap, M_oe, E1, eout, dout);
}

// round 8
// speedup vs baseline: 10.9233x; 2.0163x over previous
#include <cuda_runtime.h>
#include <cstdint>

// ---------------- scratch (device globals; no allocation allowed) -------------
#define MAXN 50000
#define MAXE 500000

__device__ float g_xl[MAXN * 128];
__device__ float g_xr[MAXN * 128];
__device__ float g_xcat[MAXN * 512];
__device__ float g_elog[MAXE * 16];
__device__ float g_nmax[MAXN * 16];
__device__ float g_nsum[MAXN * 16];
__device__ float g_pre[(size_t)MAXE * 128];   // dual_attr @ We1

// ---------------- helpers -----------------------------------------------------

__device__ __forceinline__ void atomicMaxF(float* addr, float v) {
    if (v >= 0.f) atomicMax((int*)addr, __float_as_int(v));
    else          atomicMin((unsigned int*)addr, __float_as_uint(v));
}

// ---------------- tiled GEMM: out[M,128] = A[M,K] @ W[K,128] (+bias) ----------
// 256 threads, 64 rows x 128 cols per block, ktile=64. Micro-tile 8x4 per thread
// with float4 A broadcast loads -> FMA-issue bound (LDS wavefronts 24 per 128
// FFMA vs 4x4's 32 per 64). smem = 48KB -> 4 blocks/SM.
template <int K>
__global__ __launch_bounds__(256)
void gemm_t(const float* __restrict__ A, const float* __restrict__ W,
            const float* __restrict__ bias, float* __restrict__ out, int M) {
    __shared__ float As[64 * 64];    // [r][k]
    __shared__ float Ws[64 * 128];   // [k][n]

    const int tid = threadIdx.x;
    const int tx = tid & 31;        // output cols tx*4 .. tx*4+3
    const int ty = tid >> 5;        // output rows ty*8 .. ty*8+7
    const int r0 = blockIdx.x * 64;

    float4 acc[8];
    float4 binit = bias ? *(const float4*)&bias[tx * 4] : make_float4(0.f, 0.f, 0.f, 0.f);
#pragma unroll
    for (int i = 0; i < 8; i++) acc[i] = binit;

    for (int kt = 0; kt < K; kt += 64) {
        // stage As[64r][64k]: 64x16 float4, coalesced (2 rows / warp)
#pragma unroll
        for (int i = 0; i < 4; i++) {
            int flat = tid + i * 256;
            int r = flat >> 4, c4 = flat & 15;
            float4 v = (r0 + r < M)
                ? *(const float4*)&A[(size_t)(r0 + r) * K + kt + c4 * 4]
                : make_float4(0.f, 0.f, 0.f, 0.f);
            *(float4*)&As[r * 64 + c4 * 4] = v;
        }
        // stage Ws[64k][128n]: 64x32 float4, coalesced (k uniform per warp)
#pragma unroll
        for (int i = 0; i < 8; i++) {
            int flat = tid + i * 256;
            int k = flat >> 5, c4 = flat & 31;
            *(float4*)&Ws[k * 128 + c4 * 4] =
                *(const float4*)&W[(size_t)(kt + k) * 128 + c4 * 4];
        }
        __syncthreads();

#pragma unroll 2
        for (int k4 = 0; k4 < 64; k4 += 4) {
            float4 w0 = *(const float4*)&Ws[(k4 + 0) * 128 + tx * 4];
            float4 w1 = *(const float4*)&Ws[(k4 + 1) * 128 + tx * 4];
            float4 w2 = *(const float4*)&Ws[(k4 + 2) * 128 + tx * 4];
            float4 w3 = *(const float4*)&Ws[(k4 + 3) * 128 + tx * 4];
#pragma unroll
            for (int r = 0; r < 8; r++) {
                float4 a = *(const float4*)&As[(ty * 8 + r) * 64 + k4];  // broadcast
                acc[r].x += a.x * w0.x + a.y * w1.x + a.z * w2.x + a.w * w3.x;
                acc[r].y += a.x * w0.y + a.y * w1.y + a.z * w2.y + a.w * w3.y;
                acc[r].z += a.x * w0.z + a.y * w1.z + a.z * w2.z + a.w * w3.z;
                acc[r].w += a.x * w0.w + a.y * w1.w + a.z * w2.w + a.w * w3.w;
            }
        }
        __syncthreads();
    }

#pragma unroll
    for (int r = 0; r < 8; r++) {
        int row = r0 + ty * 8 + r;
        if (row < M) *(float4*)&out[(size_t)row * 128 + tx * 4] = acc[r];
    }
}

// xcat[n, c*128+j] = b_c[j]  (bias init of the concatenated conv outputs), float4
__global__ void init_xcat(float* __restrict__ xcat,
                          const float* __restrict__ b1, const float* __restrict__ b2,
                          const float* __restrict__ b3, const float* __restrict__ b4, int N) {
    int idx = blockIdx.x * blockDim.x + threadIdx.x;
    if (idx >= N * 128) return;
    int col4 = idx & 127;
    int c = col4 >> 5, j4 = col4 & 31;
    const float* b = (c == 0) ? b1 : (c == 1) ? b2 : (c == 2) ? b3 : b4;
    *(float4*)&xcat[(size_t)idx * 4] = *(const float4*)&b[j4 * 4];
}

__global__ void init_ns(float* __restrict__ nmax, float* __restrict__ nsum, int n) {
    int idx = blockIdx.x * blockDim.x + threadIdx.x;
    if (idx < n) {
        nmax[idx] = __int_as_float(0xff800000);  // -inf
        nsum[idx] = 0.f;
    }
}

// Pass A: per-edge logits; 32 threads (1 warp) per edge, 8 edges / 256-thread block.
template <bool HASE>
__global__ void edge_logits(const int* __restrict__ src, const int* __restrict__ dst, int E,
                            const float* __restrict__ xl, const float* __restrict__ xr,
                            const float* __restrict__ pre,
                            const float* __restrict__ att, float* __restrict__ elog,
                            float* __restrict__ nmax) {
    const int l = threadIdx.x & 31;
    const int slot = threadIdx.x >> 5;
    const int e = blockIdx.x * 8 + slot;
    if (e >= E) return;
    int s = src[e], d = dst[e];
    float4 a = *(const float4*)&xl[(size_t)s * 128 + l * 4];
    float4 b = *(const float4*)&xr[(size_t)d * 128 + l * 4];
    float4 m = make_float4(a.x + b.x, a.y + b.y, a.z + b.z, a.w + b.w);
    if (HASE) {
        float4 p = *(const float4*)&pre[(size_t)e * 128 + l * 4];
        m.x += p.x; m.y += p.y; m.z += p.z; m.w += p.w;
    }
    float4 t4 = *(const float4*)&att[l * 4];
    float lx = (m.x > 0.f) ? m.x : 0.2f * m.x;
    float ly = (m.y > 0.f) ? m.y : 0.2f * m.y;
    float lz = (m.z > 0.f) ? m.z : 0.2f * m.z;
    float lw = (m.w > 0.f) ? m.w : 0.2f * m.w;
    float partial = lx * t4.x + ly * t4.y + lz * t4.z + lw * t4.w;
    partial += __shfl_xor_sync(0xffffffffu, partial, 1);   // 2 lanes per head

    if ((l & 1) == 0) {
        int h = l >> 1;
        elog[(size_t)e * 16 + h] = partial;
        atomicMaxF(&nmax[(size_t)d * 16 + h], partial);
    }
}

// Pass B: e = exp(logit - max[dst]); accumulate segment sums (vectorized x4).
__global__ void edge_exp(const int* __restrict__ dst, int E,
                         const float* __restrict__ nmax, float* __restrict__ elog,
                         float* __restrict__ nsum) {
    int idx = blockIdx.x * blockDim.x + threadIdx.x;
    if (idx >= E * 4) return;
    int e = idx >> 2, q = idx & 3;
    int d = dst[e];
    float4 lg = *(const float4*)&elog[(size_t)e * 16 + q * 4];
    float4 mx = *(const float4*)&nmax[(size_t)d * 16 + q * 4];
    float4 v;
    v.x = __expf(lg.x - mx.x);
    v.y = __expf(lg.y - mx.y);
    v.z = __expf(lg.z - mx.z);
    v.w = __expf(lg.w - mx.w);
    *(float4*)&elog[(size_t)e * 16 + q * 4] = v;
    float* p = &nsum[(size_t)d * 16 + q * 4];
    asm volatile("red.global.add.v4.f32 [%0], {%1,%2,%3,%4};" ::
                 "l"(p), "f"(v.x), "f"(v.y), "f"(v.z), "f"(v.w) : "memory");
}

// Pass C: alpha-weighted scatter of xl[src] into xcat[dst] (vector RED).
__global__ void edge_agg(const int* __restrict__ src, const int* __restrict__ dst, int E,
                         const float* __restrict__ elog, const float* __restrict__ nsum,
                         const float* __restrict__ xl, float* __restrict__ xcat, int cofs) {
    const int l = threadIdx.x & 31;
    const int slot = threadIdx.x >> 5;
    const int e = blockIdx.x * 8 + slot;
    if (e >= E) return;
    int s = src[e], d = dst[e];
    int h = l >> 1;
    float alpha = elog[(size_t)e * 16 + h] / (nsum[(size_t)d * 16 + h] + 1e-16f);
    float4 v = *(const float4*)&xl[(size_t)s * 128 + l * 4];
    float* p = &xcat[(size_t)d * 512 + cofs + l * 4];
    asm volatile("red.global.add.v4.f32 [%0], {%1,%2,%3,%4};" ::
                 "l"(p), "f"(alpha * v.x), "f"(alpha * v.y),
                 "f"(alpha * v.z), "f"(alpha * v.w) : "memory");
}

// ---------------- persistent edge MLP -----------------------------------------
// 512 threads, mlp_W fully cached in smem (128 KB). Each warp owns 4 edges per
// batch: LN+relu into warp-private ps rows, then matvec reusing each W LDS.128
// across 4 edges x 4 outputs. No block sync in the mainloop.
__global__ __launch_bounds__(512, 1)
void edge_mlp(const int* __restrict__ src, const int* __restrict__ dst, int E,
              const float* __restrict__ xf,
              const float* __restrict__ lng, const float* __restrict__ lnb,
              const float* __restrict__ W, const float* __restrict__ mlpb,
              const float* __restrict__ eattr, float* __restrict__ out) {
    extern __shared__ float sm[];
    float* Ws = sm;                 // 256*128 = 32768
    float* ps = sm + 32768;         // 64 edges * 256
    float* lg = ps + 64 * 256;      // 256
    float* lb = lg + 256;           // 256
    float* mb = lb + 256;           // 128

    const int tid = threadIdx.x;
    const int l = tid & 31;
    const int w = tid >> 5;         // warp 0..15

    // stage weights + consts (coalesced)
#pragma unroll
    for (int i = tid; i < 8192; i += 512)
        *(float4*)&Ws[i * 4] = *(const float4*)&W[(size_t)i * 4];
    if (tid < 256) { lg[tid] = lng[tid]; lb[tid] = lnb[tid]; }
    if (tid < 128) mb[tid] = mlpb[tid];
    __syncthreads();

    float* psw = &ps[(w * 4) * 256];   // warp-private 4 rows

    for (int base = blockIdx.x * 64; base < E; base += gridDim.x * 64) {
        // ---- LN + relu into ps (warp-local) ----
#pragma unroll
        for (int e = 0; e < 4; e++) {
            int ge = base + w * 4 + e;
            float4 ra, rb;
            if (ge < E) {
                int s = src[ge], d = dst[ge];
                float4 a = *(const float4*)&xf[(size_t)s * 128 + l * 4];
                float4 b = *(const float4*)&xf[(size_t)d * 128 + l * 4];
                float sum = a.x + a.y + a.z + a.w + b.x + b.y + b.z + b.w;
                float sq  = a.x * a.x + a.y * a.y + a.z * a.z + a.w * a.w
                          + b.x * b.x + b.y * b.y + b.z * b.z + b.w * b.w;
#pragma unroll
                for (int off = 16; off; off >>= 1) {
                    sum += __shfl_xor_sync(0xffffffffu, sum, off);
                    sq  += __shfl_xor_sync(0xffffffffu, sq, off);
                }
                float mu = sum * (1.f / 256.f);
                float var = sq * (1.f / 256.f) - mu * mu;
                float rs = rsqrtf(var + 1e-5f);
                float4 ga = *(const float4*)&lg[l * 4];
                float4 ba = *(const float4*)&lb[l * 4];
                float4 gb = *(const float4*)&lg[128 + l * 4];
                float4 bb = *(const float4*)&lb[128 + l * 4];
                ra.x = fmaxf(0.f, (a.x - mu) * rs * ga.x + ba.x);
                ra.y = fmaxf(0.f, (a.y - mu) * rs * ga.y + ba.y);
                ra.z = fmaxf(0.f, (a.z - mu) * rs * ga.z + ba.z);
                ra.w = fmaxf(0.f, (a.w - mu) * rs * ga.w + ba.w);
                rb.x = fmaxf(0.f, (b.x - mu) * rs * gb.x + bb.x);
                rb.y = fmaxf(0.f, (b.y - mu) * rs * gb.y + bb.y);
                rb.z = fmaxf(0.f, (b.z - mu) * rs * gb.z + bb.z);
                rb.w = fmaxf(0.f, (b.w - mu) * rs * gb.w + bb.w);
            } else {
                ra = rb = make_float4(0.f, 0.f, 0.f, 0.f);
            }
            *(float4*)&psw[e * 256 + l * 4]       = ra;
            *(float4*)&psw[e * 256 + 128 + l * 4] = rb;
        }
        __syncwarp();

        // ---- matvec: 4 edges x 4 output cols per lane ----
        float4 acc0, acc1, acc2, acc3;
        float4 binit = *(const float4*)&mb[l * 4];
        acc0 = acc1 = acc2 = acc3 = binit;

#pragma unroll 2
        for (int k = 0; k < 256; k += 4) {
            float4 p0 = *(const float4*)&psw[0 * 256 + k];
            float4 p1 = *(const float4*)&psw[1 * 256 + k];
            float4 p2 = *(const float4*)&psw[2 * 256 + k];
            float4 p3 = *(const float4*)&psw[3 * 256 + k];
            const float* pp0 = &p0.x;
            const float* pp1 = &p1.x;
            const float* pp2 = &p2.x;
            const float* pp3 = &p3.x;
#pragma unroll
            for (int kk = 0; kk < 4; kk++) {
                float4 w4 = *(const float4*)&Ws[(k + kk) * 128 + l * 4];
                float q0 = pp0[kk], q1 = pp1[kk], q2 = pp2[kk], q3 = pp3[kk];
                acc0.x += q0 * w4.x; acc0.y += q0 * w4.y; acc0.z += q0 * w4.z; acc0.w += q0 * w4.w;
                acc1.x += q1 * w4.x; acc1.y += q1 * w4.y; acc1.z += q1 * w4.z; acc1.w += q1 * w4.w;
                acc2.x += q2 * w4.x; acc2.y += q2 * w4.y; acc2.z += q2 * w4.z; acc2.w += q2 * w4.w;
                acc3.x += q3 * w4.x; acc3.y += q3 * w4.y; acc3.z += q3 * w4.z; acc3.w += q3 * w4.w;
            }
        }

        // ---- epilogue: + edge_attr, store ----
        float4 accs[4] = {acc0, acc1, acc2, acc3};
#pragma unroll
        for (int e = 0; e < 4; e++) {
            int ge = base + w * 4 + e;
            if (ge >= E) continue;
            float4 ea = *(const float4*)&eattr[(size_t)ge * 128 + l * 4];
            float4 o = make_float4(ea.x + accs[e].x, ea.y + accs[e].y,
                                   ea.z + accs[e].z, ea.w + accs[e].w);
            *(float4*)&out[(size_t)ge * 128 + l * 4] = o;
        }
    }
}

// dual_out[i] = (idx==E) ? ones : edge_attr_new[idx]
__global__ void dual_gather(const int* __restrict__ idx, int M, int E,
                            const float* __restrict__ ea, float* __restrict__ out) {
    int tid = blockIdx.x * blockDim.x + threadIdx.x;
    if (tid >= M * 32) return;
    int i = tid >> 5, l = tid & 31;
    int id = idx[i];
    float4 v;
    if (id >= E) v = make_float4(1.f, 1.f, 1.f, 1.f);
    else         v = *(const float4*)&ea[(size_t)id * 128 + l * 4];
    *(float4*)&out[(size_t)i * 128 + l * 4] = v;
}

// ---------------- host orchestration ------------------------------------------

static const int MLP_SMEM = (32768 + 64 * 256 + 256 + 256 + 128) * 4;   // ~195 KB

extern "C" void kernel_launch(void* const* d_in, const int* in_sizes, int n_in,
                              void* d_out, int out_size) {
    const float* x         = (const float*)d_in[0];
    const int*   ei[4]     = {(const int*)d_in[1], (const int*)d_in[2],
                              (const int*)d_in[3], (const int*)d_in[4]};
    const float* dual_attr = (const float*)d_in[5];
    const float* edge_attr = (const float*)d_in[6];
    const int*   oemap     = (const int*)d_in[7];

    const float *Wl[4], *Wr[4], *att[4], *bb[4];
    int p = 8;
    for (int c = 0; c < 4; c++) {
        Wl[c]  = (const float*)d_in[p++];
        Wr[c]  = (const float*)d_in[p++];
        att[c] = (const float*)d_in[p++];
        bb[c]  = (const float*)d_in[p++];
    }
    const float* We1    = (const float*)d_in[24];
    const float* fuse_W = (const float*)d_in[25];
    const float* fuse_b = (const float*)d_in[26];
    const float* ln_g   = (const float*)d_in[27];
    const float* ln_b   = (const float*)d_in[28];
    const float* mlp_W  = (const float*)d_in[29];
    const float* mlp_b  = (const float*)d_in[30];

    const int N     = in_sizes[0] / 128;
    const int Ec[4] = {in_sizes[1] / 2, in_sizes[2] / 2, in_sizes[3] / 2, in_sizes[4] / 2};
    const int M_oe  = in_sizes[7];
    const int E1    = Ec[0];

    float *xl, *xr, *xcat, *elog, *nmax, *nsum, *pre;
    cudaGetSymbolAddress((void**)&xl,   g_xl);
    cudaGetSymbolAddress((void**)&xr,   g_xr);
    cudaGetSymbolAddress((void**)&xcat, g_xcat);
    cudaGetSymbolAddress((void**)&elog, g_elog);
    cudaGetSymbolAddress((void**)&nmax, g_nmax);
    cudaGetSymbolAddress((void**)&nsum, g_nsum);
    cudaGetSymbolAddress((void**)&pre,  g_pre);

    cudaFuncSetAttribute(edge_mlp, cudaFuncAttributeMaxDynamicSharedMemorySize, MLP_SMEM);

    // pre = dual_attr @ We1 (removes per-edge matvec from edge_logits)
    gemm_t<128><<<(E1 + 63) / 64, 256>>>(dual_attr, We1, nullptr, pre, E1);

    init_xcat<<<(N * 128 + 255) / 256, 256>>>(xcat, bb[0], bb[1], bb[2], bb[3], N);

    for (int c = 0; c < 4; c++) {
        const int E = Ec[c];
        const int* src = ei[c];
        const int* dst = ei[c] + E;

        gemm_t<128><<<(N + 63) / 64, 256>>>(x, Wl[c], nullptr, xl, N);
        gemm_t<128><<<(N + 63) / 64, 256>>>(x, Wr[c], nullptr, xr, N);
        init_ns<<<(N * 16 + 255) / 256, 256>>>(nmax, nsum, N * 16);

        if (c == 0)
            edge_logits<true><<<(E + 7) / 8, 256>>>(src, dst, E, xl, xr, pre,
                                                    att[c], elog, nmax);
        else
            edge_logits<false><<<(E + 7) / 8, 256>>>(src, dst, E, xl, xr, nullptr,
                                                     att[c], elog, nmax);

        edge_exp<<<(E * 4 + 255) / 256, 256>>>(dst, E, nmax, elog, nsum);
        edge_agg<<<(E + 7) / 8, 256>>>(src, dst, E, elog, nsum, xl, xcat, c * 128);
    }

    // fuse: xf = xcat @ fuse_W + fuse_b  -> output section 0
    float* xf = (float*)d_out;
    gemm_t<512><<<(N + 63) / 64, 256>>>(xcat, fuse_W, fuse_b, xf, N);

    // edge MLP -> output section 1 (persistent, W cached in smem)
    float* eout = (float*)d_out + (size_t)N * 128;
    edge_mlp<<<152, 512, MLP_SMEM>>>(ei[0], ei[0] + E1, E1, xf, ln_g, ln_b,
                                     mlp_W, mlp_b, edge_attr, eout);

    // dual gather -> output section 2
    float* dout = eout + (size_t)E1 * 128;
    dual_gather<<<(M_oe * 32 + 255) / 256, 256>>>(oemap, M_oe, E1, eout, dout);
}

// round 9
// speedup vs baseline: 17.2685x; 1.5809x over previous
#include <cuda_runtime.h>
#include <cstdint>

// ---------------- scratch (device globals; no allocation allowed) -------------
#define MAXN 50000
#define MAXE 500000

__device__ float g_xl[MAXN * 128];
__device__ float g_xr[MAXN * 128];
__device__ float g_xcat[MAXN * 512];
__device__ float g_elog[MAXE * 16];
__device__ float g_nmax[MAXN * 16];
__device__ float g_nsum[MAXN * 16];
__device__ float g_pre[(size_t)MAXE * 128];   // dual_attr @ We1

// ---------------- helpers -----------------------------------------------------

__device__ __forceinline__ void atomicMaxF(float* addr, float v) {
    if (v >= 0.f) atomicMax((int*)addr, __float_as_int(v));
    else          atomicMin((unsigned int*)addr, __float_as_uint(v));
}

__device__ __forceinline__ uint32_t tf32u(float x) {
    uint32_t u; asm("cvt.rna.tf32.f32 %0, %1;" : "=r"(u) : "f"(x)); return u;
}
__device__ __forceinline__ float4 tf32cvt4(float4 v) {
    float4 r;
    r.x = __uint_as_float(tf32u(v.x));
    r.y = __uint_as_float(tf32u(v.y));
    r.z = __uint_as_float(tf32u(v.z));
    r.w = __uint_as_float(tf32u(v.w));
    return r;
}
__device__ __forceinline__ void mma_tf32(float* c, const uint32_t* a, const uint32_t* b) {
    asm volatile(
        "mma.sync.aligned.m16n8k8.row.col.f32.tf32.tf32.f32 "
        "{%0,%1,%2,%3}, {%4,%5,%6,%7}, {%8,%9}, {%0,%1,%2,%3};\n"
        : "+f"(c[0]), "+f"(c[1]), "+f"(c[2]), "+f"(c[3])
        : "r"(a[0]), "r"(a[1]), "r"(a[2]), "r"(a[3]), "r"(b[0]), "r"(b[1]));
}

// ---------------- tf32 tensor-core GEMM: out[M,128] = A[M,K] @ W[K,128] (+bias)
// 256 threads (8 warps: 4 along m, 2 along n). Block tile 128x128, ktile 32.
// Warp tile 32x64 = 2 m16-tiles x 8 n8-tiles. Smem pads chosen so all fragment
// LDS are bank-conflict-free: As stride 36 (bank=4g+tg), Ws stride 136 (8tg+g).
template <int K>
__global__ __launch_bounds__(256)
void gemm_mma(const float* __restrict__ A, const float* __restrict__ W,
              const float* __restrict__ bias, float* __restrict__ out, int M) {
    __shared__ float As[128][36];   // [m][k]
    __shared__ float Ws[32][136];   // [k][n]

    const int tid = threadIdx.x;
    const int l = tid & 31, w = tid >> 5;
    const int g = l >> 2, tg = l & 3;
    const int wm = (w & 3) * 32;    // warp m offset
    const int wn = (w >> 2) * 64;   // warp n offset
    const int r0 = blockIdx.x * 128;

    float c[2][8][4];
#pragma unroll
    for (int mt = 0; mt < 2; mt++)
#pragma unroll
        for (int nt = 0; nt < 8; nt++)
#pragma unroll
            for (int i = 0; i < 4; i++) c[mt][nt][i] = 0.f;

    for (int kt = 0; kt < K; kt += 32) {
        // stage A tile [128 rows][32 k] (tf32-converted), coalesced float4
#pragma unroll
        for (int i = 0; i < 4; i++) {
            int flat = tid + i * 256;
            int r = flat >> 3, kq = flat & 7;
            float4 v = (r0 + r < M)
                ? *(const float4*)&A[(size_t)(r0 + r) * K + kt + kq * 4]
                : make_float4(0.f, 0.f, 0.f, 0.f);
            *(float4*)&As[r][kq * 4] = tf32cvt4(v);
        }
        // stage W tile [32 k][128 n] (tf32-converted), coalesced float4
#pragma unroll
        for (int i = 0; i < 4; i++) {
            int flat = tid + i * 256;
            int k = flat >> 5, n4 = flat & 31;
            float4 v = *(const float4*)&W[(size_t)(kt + k) * 128 + n4 * 4];
            *(float4*)&Ws[k][n4 * 4] = tf32cvt4(v);
        }
        __syncthreads();

#pragma unroll
        for (int k8 = 0; k8 < 4; k8++) {
            const int kb = k8 * 8;
            uint32_t a[2][4], b[8][2];
#pragma unroll
            for (int mt = 0; mt < 2; mt++) {
                int m = wm + mt * 16;
                a[mt][0] = __float_as_uint(As[m + g][kb + tg]);
                a[mt][1] = __float_as_uint(As[m + 8 + g][kb + tg]);
                a[mt][2] = __float_as_uint(As[m + g][kb + tg + 4]);
                a[mt][3] = __float_as_uint(As[m + 8 + g][kb + tg + 4]);
            }
#pragma unroll
            for (int nt = 0; nt < 8; nt++) {
                int n = wn + nt * 8;
                b[nt][0] = __float_as_uint(Ws[kb + tg][n + g]);
                b[nt][1] = __float_as_uint(Ws[kb + tg + 4][n + g]);
            }
#pragma unroll
            for (int mt = 0; mt < 2; mt++)
#pragma unroll
                for (int nt = 0; nt < 8; nt++)
                    mma_tf32(c[mt][nt], a[mt], b[nt]);
        }
        __syncthreads();
    }

    // epilogue: c0,c1 -> (row, col..col+1); c2,c3 -> (row+8, ...)
#pragma unroll
    for (int mt = 0; mt < 2; mt++) {
#pragma unroll
        for (int nt = 0; nt < 8; nt++) {
            int row = r0 + wm + mt * 16 + g;
            int col = wn + nt * 8 + tg * 2;
            float2 bv = bias ? *(const float2*)&bias[col] : make_float2(0.f, 0.f);
            if (row < M) {
                float2 o = make_float2(c[mt][nt][0] + bv.x, c[mt][nt][1] + bv.y);
                *(float2*)&out[(size_t)row * 128 + col] = o;
            }
            if (row + 8 < M) {
                float2 o = make_float2(c[mt][nt][2] + bv.x, c[mt][nt][3] + bv.y);
                *(float2*)&out[(size_t)(row + 8) * 128 + col] = o;
            }
        }
    }
}

// xcat[n, c*128+j] = b_c[j]  (bias init of the concatenated conv outputs), float4
__global__ void init_xcat(float* __restrict__ xcat,
                          const float* __restrict__ b1, const float* __restrict__ b2,
                          const float* __restrict__ b3, const float* __restrict__ b4, int N) {
    int idx = blockIdx.x * blockDim.x + threadIdx.x;
    if (idx >= N * 128) return;
    int col4 = idx & 127;
    int c = col4 >> 5, j4 = col4 & 31;
    const float* b = (c == 0) ? b1 : (c == 1) ? b2 : (c == 2) ? b3 : b4;
    *(float4*)&xcat[(size_t)idx * 4] = *(const float4*)&b[j4 * 4];
}

__global__ void init_ns(float* __restrict__ nmax, float* __restrict__ nsum, int n) {
    int idx = blockIdx.x * blockDim.x + threadIdx.x;
    if (idx < n) {
        nmax[idx] = __int_as_float(0xff800000);  // -inf
        nsum[idx] = 0.f;
    }
}

// Pass A: per-edge logits; 32 threads (1 warp) per edge, 8 edges / 256-thread block.
template <bool HASE>
__global__ void edge_logits(const int* __restrict__ src, const int* __restrict__ dst, int E,
                            const float* __restrict__ xl, const float* __restrict__ xr,
                            const float* __restrict__ pre,
                            const float* __restrict__ att, float* __restrict__ elog,
                            float* __restrict__ nmax) {
    const int l = threadIdx.x & 31;
    const int slot = threadIdx.x >> 5;
    const int e = blockIdx.x * 8 + slot;
    if (e >= E) return;
    int s = src[e], d = dst[e];
    float4 a = *(const float4*)&xl[(size_t)s * 128 + l * 4];
    float4 b = *(const float4*)&xr[(size_t)d * 128 + l * 4];
    float4 m = make_float4(a.x + b.x, a.y + b.y, a.z + b.z, a.w + b.w);
    if (HASE) {
        float4 p = *(const float4*)&pre[(size_t)e * 128 + l * 4];
        m.x += p.x; m.y += p.y; m.z += p.z; m.w += p.w;
    }
    float4 t4 = *(const float4*)&att[l * 4];
    float lx = (m.x > 0.f) ? m.x : 0.2f * m.x;
    float ly = (m.y > 0.f) ? m.y : 0.2f * m.y;
    float lz = (m.z > 0.f) ? m.z : 0.2f * m.z;
    float lw = (m.w > 0.f) ? m.w : 0.2f * m.w;
    float partial = lx * t4.x + ly * t4.y + lz * t4.z + lw * t4.w;
    partial += __shfl_xor_sync(0xffffffffu, partial, 1);   // 2 lanes per head

    if ((l & 1) == 0) {
        int h = l >> 1;
        elog[(size_t)e * 16 + h] = partial;
        atomicMaxF(&nmax[(size_t)d * 16 + h], partial);
    }
}

// Pass B: e = exp(logit - max[dst]); accumulate segment sums (vectorized x4).
__global__ void edge_exp(const int* __restrict__ dst, int E,
                         const float* __restrict__ nmax, float* __restrict__ elog,
                         float* __restrict__ nsum) {
    int idx = blockIdx.x * blockDim.x + threadIdx.x;
    if (idx >= E * 4) return;
    int e = idx >> 2, q = idx & 3;
    int d = dst[e];
    float4 lg = *(const float4*)&elog[(size_t)e * 16 + q * 4];
    float4 mx = *(const float4*)&nmax[(size_t)d * 16 + q * 4];
    float4 v;
    v.x = __expf(lg.x - mx.x);
    v.y = __expf(lg.y - mx.y);
    v.z = __expf(lg.z - mx.z);
    v.w = __expf(lg.w - mx.w);
    *(float4*)&elog[(size_t)e * 16 + q * 4] = v;
    float* p = &nsum[(size_t)d * 16 + q * 4];
    asm volatile("red.global.add.v4.f32 [%0], {%1,%2,%3,%4};" ::
                 "l"(p), "f"(v.x), "f"(v.y), "f"(v.z), "f"(v.w) : "memory");
}

// Pass C: alpha-weighted scatter of xl[src] into xcat[dst] (vector RED).
__global__ void edge_agg(const int* __restrict__ src, const int* __restrict__ dst, int E,
                         const float* __restrict__ elog, const float* __restrict__ nsum,
                         const float* __restrict__ xl, float* __restrict__ xcat, int cofs) {
    const int l = threadIdx.x & 31;
    const int slot = threadIdx.x >> 5;
    const int e = blockIdx.x * 8 + slot;
    if (e >= E) return;
    int s = src[e], d = dst[e];
    int h = l >> 1;
    float alpha = elog[(size_t)e * 16 + h] / (nsum[(size_t)d * 16 + h] + 1e-16f);
    float4 v = *(const float4*)&xl[(size_t)s * 128 + l * 4];
    float* p = &xcat[(size_t)d * 512 + cofs + l * 4];
    asm volatile("red.global.add.v4.f32 [%0], {%1,%2,%3,%4};" ::
                 "l"(p), "f"(alpha * v.x), "f"(alpha * v.y),
                 "f"(alpha * v.z), "f"(alpha * v.w) : "memory");
}

// ---------------- persistent edge MLP (tensor-core matvec batch) ---------------
// 256 threads. mlp_W tf32-staged once in smem [256][136]. Per 64-edge batch:
// LN+relu into tf32 ps[64][260], then block GEMM [64,256]@[256,128] via
// m16n8k8 mma (warp grid 2m x 4n). Pads make all fragment LDS conflict-free.
__global__ __launch_bounds__(256, 1)
void edge_mlp(const int* __restrict__ src, const int* __restrict__ dst, int E,
              const float* __restrict__ xf,
              const float* __restrict__ lng, const float* __restrict__ lnb,
              const float* __restrict__ W, const float* __restrict__ mlpb,
              const float* __restrict__ eattr, float* __restrict__ out) {
    extern __shared__ float sm[];
    float (*Wks)[136] = (float(*)[136])sm;                 // 256*136
    float (*ps)[260]  = (float(*)[260])(sm + 256 * 136);   // 64*260
    float* lg = sm + 256 * 136 + 64 * 260;                 // 256
    float* lb = lg + 256;                                  // 256
    float* mb = lb + 256;                                  // 128

    const int tid = threadIdx.x;
    const int l = tid & 31, w = tid >> 5;
    const int g = l >> 2, tg = l & 3;
    const int wm = (w & 1) * 32;     // 2 m-warps
    const int wn = (w >> 1) * 32;    // 4 n-warps x 32 cols

    // stage mlp_W (tf32) + consts, coalesced
#pragma unroll
    for (int i = 0; i < 32; i++) {
        int flat = tid + i * 256;
        int k = flat >> 5, n4 = flat & 31;
        float4 v = *(const float4*)&W[(size_t)k * 128 + n4 * 4];
        *(float4*)&Wks[k][n4 * 4] = tf32cvt4(v);
    }
    lg[tid] = lng[tid]; lb[tid] = lnb[tid];
    if (tid < 128) mb[tid] = mlpb[tid];
    __syncthreads();

    for (int base = blockIdx.x * 64; base < E; base += gridDim.x * 64) {
        // ---- LN + relu into ps (8 edges per warp) ----
#pragma unroll
        for (int e = 0; e < 8; e++) {
            int le = w * 8 + e;
            int ge = base + le;
            float4 ra, rb;
            if (ge < E) {
                int s = src[ge], d = dst[ge];
                float4 a = *(const float4*)&xf[(size_t)s * 128 + l * 4];
                float4 b = *(const float4*)&xf[(size_t)d * 128 + l * 4];
                float sum = a.x + a.y + a.z + a.w + b.x + b.y + b.z + b.w;
                float sq  = a.x * a.x + a.y * a.y + a.z * a.z + a.w * a.w
                          + b.x * b.x + b.y * b.y + b.z * b.z + b.w * b.w;
#pragma unroll
                for (int off = 16; off; off >>= 1) {
                    sum += __shfl_xor_sync(0xffffffffu, sum, off);
                    sq  += __shfl_xor_sync(0xffffffffu, sq, off);
                }
                float mu = sum * (1.f / 256.f);
                float var = sq * (1.f / 256.f) - mu * mu;
                float rs = rsqrtf(var + 1e-5f);
                float4 ga = *(const float4*)&lg[l * 4];
                float4 ba = *(const float4*)&lb[l * 4];
                float4 gb = *(const float4*)&lg[128 + l * 4];
                float4 bb = *(const float4*)&lb[128 + l * 4];
                ra.x = fmaxf(0.f, (a.x - mu) * rs * ga.x + ba.x);
                ra.y = fmaxf(0.f, (a.y - mu) * rs * ga.y + ba.y);
                ra.z = fmaxf(0.f, (a.z - mu) * rs * ga.z + ba.z);
                ra.w = fmaxf(0.f, (a.w - mu) * rs * ga.w + ba.w);
                rb.x = fmaxf(0.f, (b.x - mu) * rs * gb.x + bb.x);
                rb.y = fmaxf(0.f, (b.y - mu) * rs * gb.y + bb.y);
                rb.z = fmaxf(0.f, (b.z - mu) * rs * gb.z + bb.z);
                rb.w = fmaxf(0.f, (b.w - mu) * rs * gb.w + bb.w);
            } else {
                ra = rb = make_float4(0.f, 0.f, 0.f, 0.f);
            }
            *(float4*)&ps[le][l * 4]       = tf32cvt4(ra);
            *(float4*)&ps[le][128 + l * 4] = tf32cvt4(rb);
        }
        __syncthreads();

        // ---- block GEMM [64,256]@[256,128] ----
        float c[2][4][4];
#pragma unroll
        for (int mt = 0; mt < 2; mt++)
#pragma unroll
            for (int nt = 0; nt < 4; nt++)
#pragma unroll
                for (int i = 0; i < 4; i++) c[mt][nt][i] = 0.f;

#pragma unroll 4
        for (int k8 = 0; k8 < 32; k8++) {
            const int kb = k8 * 8;
            uint32_t a[2][4], b[4][2];
#pragma unroll
            for (int mt = 0; mt < 2; mt++) {
                int m = wm + mt * 16;
                a[mt][0] = __float_as_uint(ps[m + g][kb + tg]);
                a[mt][1] = __float_as_uint(ps[m + 8 + g][kb + tg]);
                a[mt][2] = __float_as_uint(ps[m + g][kb + tg + 4]);
                a[mt][3] = __float_as_uint(ps[m + 8 + g][kb + tg + 4]);
            }
#pragma unroll
            for (int nt = 0; nt < 4; nt++) {
                int n = wn + nt * 8;
                b[nt][0] = __float_as_uint(Wks[kb + tg][n + g]);
                b[nt][1] = __float_as_uint(Wks[kb + tg + 4][n + g]);
            }
#pragma unroll
            for (int mt = 0; mt < 2; mt++)
#pragma unroll
                for (int nt = 0; nt < 4; nt++)
                    mma_tf32(c[mt][nt], a[mt], b[nt]);
        }

        // ---- epilogue: + mlp_b + edge_attr, store ----
#pragma unroll
        for (int mt = 0; mt < 2; mt++) {
#pragma unroll
            for (int nt = 0; nt < 4; nt++) {
                int le = wm + mt * 16 + g;
                int col = wn + nt * 8 + tg * 2;
                float2 bv = *(const float2*)&mb[col];
                int ge0 = base + le;
                int ge1 = ge0 + 8;
                if (ge0 < E) {
                    float2 ea = *(const float2*)&eattr[(size_t)ge0 * 128 + col];
                    float2 o = make_float2(c[mt][nt][0] + bv.x + ea.x,
                                           c[mt][nt][1] + bv.y + ea.y);
                    *(float2*)&out[(size_t)ge0 * 128 + col] = o;
                }
                if (ge1 < E) {
                    float2 ea = *(const float2*)&eattr[(size_t)ge1 * 128 + col];
                    float2 o = make_float2(c[mt][nt][2] + bv.x + ea.x,
                                           c[mt][nt][3] + bv.y + ea.y);
                    *(float2*)&out[(size_t)ge1 * 128 + col] = o;
                }
            }
        }
        __syncthreads();   // ps reused next batch
    }
}

// dual_out[i] = (idx==E) ? ones : edge_attr_new[idx]
__global__ void dual_gather(const int* __restrict__ idx, int M, int E,
                            const float* __restrict__ ea, float* __restrict__ out) {
    int tid = blockIdx.x * blockDim.x + threadIdx.x;
    if (tid >= M * 32) return;
    int i = tid >> 5, l = tid & 31;
    int id = idx[i];
    float4 v;
    if (id >= E) v = make_float4(1.f, 1.f, 1.f, 1.f);
    else         v = *(const float4*)&ea[(size_t)id * 128 + l * 4];
    *(float4*)&out[(size_t)i * 128 + l * 4] = v;
}

// ---------------- host orchestration ------------------------------------------

static const int MLP_SMEM = (256 * 136 + 64 * 260 + 256 + 256 + 128) * 4;  // ~204 KB

extern "C" void kernel_launch(void* const* d_in, const int* in_sizes, int n_in,
                              void* d_out, int out_size) {
    const float* x         = (const float*)d_in[0];
    const int*   ei[4]     = {(const int*)d_in[1], (const int*)d_in[2],
                              (const int*)d_in[3], (const int*)d_in[4]};
    const float* dual_attr = (const float*)d_in[5];
    const float* edge_attr = (const float*)d_in[6];
    const int*   oemap     = (const int*)d_in[7];

    const float *Wl[4], *Wr[4], *att[4], *bb[4];
    int p = 8;
    for (int c = 0; c < 4; c++) {
        Wl[c]  = (const float*)d_in[p++];
        Wr[c]  = (const float*)d_in[p++];
        att[c] = (const float*)d_in[p++];
        bb[c]  = (const float*)d_in[p++];
    }
    const float* We1    = (const float*)d_in[24];
    const float* fuse_W = (const float*)d_in[25];
    const float* fuse_b = (const float*)d_in[26];
    const float* ln_g   = (const float*)d_in[27];
    const float* ln_b   = (const float*)d_in[28];
    const float* mlp_W  = (const float*)d_in[29];
    const float* mlp_b  = (const float*)d_in[30];

    const int N     = in_sizes[0] / 128;
    const int Ec[4] = {in_sizes[1] / 2, in_sizes[2] / 2, in_sizes[3] / 2, in_sizes[4] / 2};
    const int M_oe  = in_sizes[7];
    const int E1    = Ec[0];

    float *xl, *xr, *xcat, *elog, *nmax, *nsum, *pre;
    cudaGetSymbolAddress((void**)&xl,   g_xl);
    cudaGetSymbolAddress((void**)&xr,   g_xr);
    cudaGetSymbolAddress((void**)&xcat, g_xcat);
    cudaGetSymbolAddress((void**)&elog, g_elog);
    cudaGetSymbolAddress((void**)&nmax, g_nmax);
    cudaGetSymbolAddress((void**)&nsum, g_nsum);
    cudaGetSymbolAddress((void**)&pre,  g_pre);

    cudaFuncSetAttribute(edge_mlp, cudaFuncAttributeMaxDynamicSharedMemorySize, MLP_SMEM);

    // pre = dual_attr @ We1 (removes per-edge matvec from edge_logits)
    gemm_mma<128><<<(E1 + 127) / 128, 256>>>(dual_attr, We1, nullptr, pre, E1);

    init_xcat<<<(N * 128 + 255) / 256, 256>>>(xcat, bb[0], bb[1], bb[2], bb[3], N);

    for (int c = 0; c < 4; c++) {
        const int E = Ec[c];
        const int* src = ei[c];
        const int* dst = ei[c] + E;

        gemm_mma<128><<<(N + 127) / 128, 256>>>(x, Wl[c], nullptr, xl, N);
        gemm_mma<128><<<(N + 127) / 128, 256>>>(x, Wr[c], nullptr, xr, N);
        init_ns<<<(N * 16 + 255) / 256, 256>>>(nmax, nsum, N * 16);

        if (c == 0)
            edge_logits<true><<<(E + 7) / 8, 256>>>(src, dst, E, xl, xr, pre,
                                                    att[c], elog, nmax);
        else
            edge_logits<false><<<(E + 7) / 8, 256>>>(src, dst, E, xl, xr, nullptr,
                                                     att[c], elog, nmax);

        edge_exp<<<(E * 4 + 255) / 256, 256>>>(dst, E, nmax, elog, nsum);
        edge_agg<<<(E + 7) / 8, 256>>>(src, dst, E, elog, nsum, xl, xcat, c * 128);
    }

    // fuse: xf = xcat @ fuse_W + fuse_b  -> output section 0
    float* xf = (float*)d_out;
    gemm_mma<512><<<(N + 127) / 128, 256>>>(xcat, fuse_W, fuse_b, xf, N);

    // edge MLP -> output section 1 (persistent, tensor-core batch matvec)
    float* eout = (float*)d_out + (size_t)N * 128;
    edge_mlp<<<148, 256, MLP_SMEM>>>(ei[0], ei[0] + E1, E1, xf, ln_g, ln_b,
                                     mlp_W, mlp_b, edge_attr, eout);

    // dual gather -> output section 2
    float* dout = eout + (size_t)E1 * 128;
    dual_gather<<<(M_oe * 32 + 255) / 256, 256>>>(oemap, M_oe, E1, eout, dout);
}

// round 10
// speedup vs baseline: 18.1312x; 1.0500x over previous
#include <cuda_runtime.h>
#include <cstdint>

// ---------------- scratch (device globals; no allocation allowed) -------------
#define MAXN 50000
#define MAXE 500000

__device__ float g_xlr[(size_t)MAXN * 1024];  // [N][8*128]: (Wl|Wr) x 4 convs
__device__ float g_wcat[128 * 1024];          // packed weights [k][1024]
__device__ float g_xcat[MAXN * 512];
__device__ float g_elog[MAXE * 16];
__device__ float g_nmax[MAXN * 16];
__device__ float g_nsum[MAXN * 16];
__device__ float g_pre[(size_t)MAXE * 128];   // dual_attr @ We1

// ---------------- helpers -----------------------------------------------------

__device__ __forceinline__ void atomicMaxF(float* addr, float v) {
    if (v >= 0.f) atomicMax((int*)addr, __float_as_int(v));
    else          atomicMin((unsigned int*)addr, __float_as_uint(v));
}

__device__ __forceinline__ uint32_t tf32u(float x) {
    uint32_t u; asm("cvt.rna.tf32.f32 %0, %1;" : "=r"(u) : "f"(x)); return u;
}
__device__ __forceinline__ float4 tf32cvt4(float4 v) {
    float4 r;
    r.x = __uint_as_float(tf32u(v.x));
    r.y = __uint_as_float(tf32u(v.y));
    r.z = __uint_as_float(tf32u(v.z));
    r.w = __uint_as_float(tf32u(v.w));
    return r;
}
__device__ __forceinline__ void mma_tf32(float* c, const uint32_t* a, const uint32_t* b) {
    asm volatile(
        "mma.sync.aligned.m16n8k8.row.col.f32.tf32.tf32.f32 "
        "{%0,%1,%2,%3}, {%4,%5,%6,%7}, {%8,%9}, {%0,%1,%2,%3};\n"
        : "+f"(c[0]), "+f"(c[1]), "+f"(c[2]), "+f"(c[3])
        : "r"(a[0]), "r"(a[1]), "r"(a[2]), "r"(a[3]), "r"(b[0]), "r"(b[1]));
}

// pack 8 [128,128] weight mats into wcat[k][w*128+j]
__global__ void pack_w(const float* __restrict__ w0, const float* __restrict__ w1,
                       const float* __restrict__ w2, const float* __restrict__ w3,
                       const float* __restrict__ w4, const float* __restrict__ w5,
                       const float* __restrict__ w6, const float* __restrict__ w7,
                       float* __restrict__ wcat) {
    int idx = blockIdx.x * blockDim.x + threadIdx.x;
    if (idx >= 128 * 1024) return;
    int w = (idx >> 14), rem = idx & 16383;
    int k = rem >> 7, j = rem & 127;
    const float* ws[8] = {w0, w1, w2, w3, w4, w5, w6, w7};
    wcat[k * 1024 + w * 128 + j] = ws[w][k * 128 + j];
}

// ---------------- tf32 tensor-core GEMM: out[M,NW] = A[M,K] @ W[K,NW] (+bias)
// Block tile 128x128 at (blockIdx.x*128, blockIdx.y*128). 256 threads, 8 warps
// (4m x 2n), warp tile 32x64, ktile 32. Pads: As stride 36, Ws stride 136 ->
// conflict-free fragment LDS.
template <int K, int NW, int OSTRIDE>
__global__ __launch_bounds__(256)
void gemm_mma(const float* __restrict__ A, const float* __restrict__ W,
              const float* __restrict__ bias, float* __restrict__ out, int M) {
    __shared__ float As[128][36];   // [m][k]
    __shared__ float Ws[32][136];   // [k][n]

    const int tid = threadIdx.x;
    const int l = tid & 31, w = tid >> 5;
    const int g = l >> 2, tg = l & 3;
    const int wm = (w & 3) * 32;
    const int wn = (w >> 2) * 64;
    const int r0 = blockIdx.x * 128;
    const int c0 = blockIdx.y * 128;

    float c[2][8][4];
#pragma unroll
    for (int mt = 0; mt < 2; mt++)
#pragma unroll
        for (int nt = 0; nt < 8; nt++)
#pragma unroll
            for (int i = 0; i < 4; i++) c[mt][nt][i] = 0.f;

    for (int kt = 0; kt < K; kt += 32) {
#pragma unroll
        for (int i = 0; i < 4; i++) {
            int flat = tid + i * 256;
            int r = flat >> 3, kq = flat & 7;
            float4 v = (r0 + r < M)
                ? *(const float4*)&A[(size_t)(r0 + r) * K + kt + kq * 4]
                : make_float4(0.f, 0.f, 0.f, 0.f);
            *(float4*)&As[r][kq * 4] = tf32cvt4(v);
        }
#pragma unroll
        for (int i = 0; i < 4; i++) {
            int flat = tid + i * 256;
            int k = flat >> 5, n4 = flat & 31;
            float4 v = *(const float4*)&W[(size_t)(kt + k) * NW + c0 + n4 * 4];
            *(float4*)&Ws[k][n4 * 4] = tf32cvt4(v);
        }
        __syncthreads();

#pragma unroll
        for (int k8 = 0; k8 < 4; k8++) {
            const int kb = k8 * 8;
            uint32_t a[2][4], b[8][2];
#pragma unroll
            for (int mt = 0; mt < 2; mt++) {
                int m = wm + mt * 16;
                a[mt][0] = __float_as_uint(As[m + g][kb + tg]);
                a[mt][1] = __float_as_uint(As[m + 8 + g][kb + tg]);
                a[mt][2] = __float_as_uint(As[m + g][kb + tg + 4]);
                a[mt][3] = __float_as_uint(As[m + 8 + g][kb + tg + 4]);
            }
#pragma unroll
            for (int nt = 0; nt < 8; nt++) {
                int n = wn + nt * 8;
                b[nt][0] = __float_as_uint(Ws[kb + tg][n + g]);
                b[nt][1] = __float_as_uint(Ws[kb + tg + 4][n + g]);
            }
#pragma unroll
            for (int mt = 0; mt < 2; mt++)
#pragma unroll
                for (int nt = 0; nt < 8; nt++)
                    mma_tf32(c[mt][nt], a[mt], b[nt]);
        }
        __syncthreads();
    }

#pragma unroll
    for (int mt = 0; mt < 2; mt++) {
#pragma unroll
        for (int nt = 0; nt < 8; nt++) {
            int row = r0 + wm + mt * 16 + g;
            int col = c0 + wn + nt * 8 + tg * 2;
            float2 bv = bias ? *(const float2*)&bias[col] : make_float2(0.f, 0.f);
            if (row < M) {
                float2 o = make_float2(c[mt][nt][0] + bv.x, c[mt][nt][1] + bv.y);
                *(float2*)&out[(size_t)row * OSTRIDE + col] = o;
            }
            if (row + 8 < M) {
                float2 o = make_float2(c[mt][nt][2] + bv.x, c[mt][nt][3] + bv.y);
                *(float2*)&out[(size_t)(row + 8) * OSTRIDE + col] = o;
            }
        }
    }
}

// xcat[n, c*128+j] = b_c[j]
__global__ void init_xcat(float* __restrict__ xcat,
                          const float* __restrict__ b1, const float* __restrict__ b2,
                          const float* __restrict__ b3, const float* __restrict__ b4, int N) {
    int idx = blockIdx.x * blockDim.x + threadIdx.x;
    if (idx >= N * 128) return;
    int col4 = idx & 127;
    int c = col4 >> 5, j4 = col4 & 31;
    const float* b = (c == 0) ? b1 : (c == 1) ? b2 : (c == 2) ? b3 : b4;
    *(float4*)&xcat[(size_t)idx * 4] = *(const float4*)&b[j4 * 4];
}

__global__ void init_ns(float* __restrict__ nmax, float* __restrict__ nsum, int n) {
    int idx = blockIdx.x * blockDim.x + threadIdx.x;
    if (idx < n) {
        nmax[idx] = __int_as_float(0xff800000);  // -inf
        nsum[idx] = 0.f;
    }
}

// Pass A: per-edge logits. xlr row stride 1024; conv c uses cols [c*256, c*256+128)
// for xl and [c*256+128, c*256+256) for xr.
template <bool HASE>
__global__ void edge_logits(const int* __restrict__ src, const int* __restrict__ dst, int E,
                            const float* __restrict__ xlr, int cofs,
                            const float* __restrict__ pre,
                            const float* __restrict__ att, float* __restrict__ elog,
                            float* __restrict__ nmax) {
    const int l = threadIdx.x & 31;
    const int slot = threadIdx.x >> 5;
    const int e = blockIdx.x * 8 + slot;
    if (e >= E) return;
    int s = src[e], d = dst[e];
    float4 a = *(const float4*)&xlr[(size_t)s * 1024 + cofs + l * 4];
    float4 b = *(const float4*)&xlr[(size_t)d * 1024 + cofs + 128 + l * 4];
    float4 m = make_float4(a.x + b.x, a.y + b.y, a.z + b.z, a.w + b.w);
    if (HASE) {
        float4 p = *(const float4*)&pre[(size_t)e * 128 + l * 4];
        m.x += p.x; m.y += p.y; m.z += p.z; m.w += p.w;
    }
    float4 t4 = *(const float4*)&att[l * 4];
    float lx = (m.x > 0.f) ? m.x : 0.2f * m.x;
    float ly = (m.y > 0.f) ? m.y : 0.2f * m.y;
    float lz = (m.z > 0.f) ? m.z : 0.2f * m.z;
    float lw = (m.w > 0.f) ? m.w : 0.2f * m.w;
    float partial = lx * t4.x + ly * t4.y + lz * t4.z + lw * t4.w;
    partial += __shfl_xor_sync(0xffffffffu, partial, 1);

    if ((l & 1) == 0) {
        int h = l >> 1;
        elog[(size_t)e * 16 + h] = partial;
        atomicMaxF(&nmax[(size_t)d * 16 + h], partial);
    }
}

// Pass B: e = exp(logit - max[dst]); accumulate segment sums (vectorized x4).
__global__ void edge_exp(const int* __restrict__ dst, int E,
                         const float* __restrict__ nmax, float* __restrict__ elog,
                         float* __restrict__ nsum) {
    int idx = blockIdx.x * blockDim.x + threadIdx.x;
    if (idx >= E * 4) return;
    int e = idx >> 2, q = idx & 3;
    int d = dst[e];
    float4 lg = *(const float4*)&elog[(size_t)e * 16 + q * 4];
    float4 mx = *(const float4*)&nmax[(size_t)d * 16 + q * 4];
    float4 v;
    v.x = __expf(lg.x - mx.x);
    v.y = __expf(lg.y - mx.y);
    v.z = __expf(lg.z - mx.z);
    v.w = __expf(lg.w - mx.w);
    *(float4*)&elog[(size_t)e * 16 + q * 4] = v;
    float* p = &nsum[(size_t)d * 16 + q * 4];
    asm volatile("red.global.add.v4.f32 [%0], {%1,%2,%3,%4};" ::
                 "l"(p), "f"(v.x), "f"(v.y), "f"(v.z), "f"(v.w) : "memory");
}

// Pass C: alpha-weighted scatter of xl[src] into xcat[dst] (vector RED).
__global__ void edge_agg(const int* __restrict__ src, const int* __restrict__ dst, int E,
                         const float* __restrict__ elog, const float* __restrict__ nsum,
                         const float* __restrict__ xlr, int cofs,
                         float* __restrict__ xcat, int xofs) {
    const int l = threadIdx.x & 31;
    const int slot = threadIdx.x >> 5;
    const int e = blockIdx.x * 8 + slot;
    if (e >= E) return;
    int s = src[e], d = dst[e];
    int h = l >> 1;
    float alpha = elog[(size_t)e * 16 + h] / (nsum[(size_t)d * 16 + h] + 1e-16f);
    float4 v = *(const float4*)&xlr[(size_t)s * 1024 + cofs + l * 4];
    float* p = &xcat[(size_t)d * 512 + xofs + l * 4];
    asm volatile("red.global.add.v4.f32 [%0], {%1,%2,%3,%4};" ::
                 "l"(p), "f"(alpha * v.x), "f"(alpha * v.y),
                 "f"(alpha * v.z), "f"(alpha * v.w) : "memory");
}

// ---------------- persistent edge MLP (tensor-core matvec batch) ---------------
// 512 threads (16 warps, 2m x 8n, warp tile 32x16). mlp_W tf32-staged in smem.
__global__ __launch_bounds__(512, 1)
void edge_mlp(const int* __restrict__ src, const int* __restrict__ dst, int E,
              const float* __restrict__ xf,
              const float* __restrict__ lng, const float* __restrict__ lnb,
              const float* __restrict__ W, const float* __restrict__ mlpb,
              const float* __restrict__ eattr, float* __restrict__ out) {
    extern __shared__ float sm[];
    float (*Wks)[136] = (float(*)[136])sm;                 // 256*136
    float (*ps)[260]  = (float(*)[260])(sm + 256 * 136);   // 64*260
    float* lg = sm + 256 * 136 + 64 * 260;                 // 256
    float* lb = lg + 256;                                  // 256
    float* mb = lb + 256;                                  // 128

    const int tid = threadIdx.x;
    const int l = tid & 31, w = tid >> 5;
    const int g = l >> 2, tg = l & 3;
    const int wm = (w & 1) * 32;     // 2 m-warps
    const int wn = (w >> 1) * 16;    // 8 n-warps x 16 cols

    // stage mlp_W (tf32) + consts, coalesced
#pragma unroll
    for (int i = 0; i < 16; i++) {
        int flat = tid + i * 512;
        int k = flat >> 5, n4 = flat & 31;
        float4 v = *(const float4*)&W[(size_t)k * 128 + n4 * 4];
        *(float4*)&Wks[k][n4 * 4] = tf32cvt4(v);
    }
    if (tid < 256) { lg[tid] = lng[tid]; lb[tid] = lnb[tid]; }
    if (tid < 128) mb[tid] = mlpb[tid];
    __syncthreads();

    for (int base = blockIdx.x * 64; base < E; base += gridDim.x * 64) {
        // ---- LN + relu into ps (4 edges per warp) ----
#pragma unroll
        for (int e = 0; e < 4; e++) {
            int le = w * 4 + e;
            int ge = base + le;
            float4 ra, rb;
            if (ge < E) {
                int s = src[ge], d = dst[ge];
                float4 a = *(const float4*)&xf[(size_t)s * 128 + l * 4];
                float4 b = *(const float4*)&xf[(size_t)d * 128 + l * 4];
                float sum = a.x + a.y + a.z + a.w + b.x + b.y + b.z + b.w;
                float sq  = a.x * a.x + a.y * a.y + a.z * a.z + a.w * a.w
                          + b.x * b.x + b.y * b.y + b.z * b.z + b.w * b.w;
#pragma unroll
                for (int off = 16; off; off >>= 1) {
                    sum += __shfl_xor_sync(0xffffffffu, sum, off);
                    sq  += __shfl_xor_sync(0xffffffffu, sq, off);
                }
                float mu = sum * (1.f / 256.f);
                float var = sq * (1.f / 256.f) - mu * mu;
                float rs = rsqrtf(var + 1e-5f);
                float4 ga = *(const float4*)&lg[l * 4];
                float4 ba = *(const float4*)&lb[l * 4];
                float4 gb = *(const float4*)&lg[128 + l * 4];
                float4 bb = *(const float4*)&lb[128 + l * 4];
                ra.x = fmaxf(0.f, (a.x - mu) * rs * ga.x + ba.x);
                ra.y = fmaxf(0.f, (a.y - mu) * rs * ga.y + ba.y);
                ra.z = fmaxf(0.f, (a.z - mu) * rs * ga.z + ba.z);
                ra.w = fmaxf(0.f, (a.w - mu) * rs * ga.w + ba.w);
                rb.x = fmaxf(0.f, (b.x - mu) * rs * gb.x + bb.x);
                rb.y = fmaxf(0.f, (b.y - mu) * rs * gb.y + bb.y);
                rb.z = fmaxf(0.f, (b.z - mu) * rs * gb.z + bb.z);
                rb.w = fmaxf(0.f, (b.w - mu) * rs * gb.w + bb.w);
            } else {
                ra = rb = make_float4(0.f, 0.f, 0.f, 0.f);
            }
            *(float4*)&ps[le][l * 4]       = tf32cvt4(ra);
            *(float4*)&ps[le][128 + l * 4] = tf32cvt4(rb);
        }
        __syncthreads();

        // ---- block GEMM [64,256]@[256,128]; warp tile 32x16 ----
        float c[2][2][4];
#pragma unroll
        for (int mt = 0; mt < 2; mt++)
#pragma unroll
            for (int nt = 0; nt < 2; nt++)
#pragma unroll
                for (int i = 0; i < 4; i++) c[mt][nt][i] = 0.f;

#pragma unroll 4
        for (int k8 = 0; k8 < 32; k8++) {
            const int kb = k8 * 8;
            uint32_t a[2][4], b[2][2];
#pragma unroll
            for (int mt = 0; mt < 2; mt++) {
                int m = wm + mt * 16;
                a[mt][0] = __float_as_uint(ps[m + g][kb + tg]);
                a[mt][1] = __float_as_uint(ps[m + 8 + g][kb + tg]);
                a[mt][2] = __float_as_uint(ps[m + g][kb + tg + 4]);
                a[mt][3] = __float_as_uint(ps[m + 8 + g][kb + tg + 4]);
            }
#pragma unroll
            for (int nt = 0; nt < 2; nt++) {
                int n = wn + nt * 8;
                b[nt][0] = __float_as_uint(Wks[kb + tg][n + g]);
                b[nt][1] = __float_as_uint(Wks[kb + tg + 4][n + g]);
            }
#pragma unroll
            for (int mt = 0; mt < 2; mt++)
#pragma unroll
                for (int nt = 0; nt < 2; nt++)
                    mma_tf32(c[mt][nt], a[mt], b[nt]);
        }

        // ---- epilogue: + mlp_b + edge_attr, store ----
#pragma unroll
        for (int mt = 0; mt < 2; mt++) {
#pragma unroll
            for (int nt = 0; nt < 2; nt++) {
                int le = wm + mt * 16 + g;
                int col = wn + nt * 8 + tg * 2;
                float2 bv = *(const float2*)&mb[col];
                int ge0 = base + le;
                int ge1 = ge0 + 8;
                if (ge0 < E) {
                    float2 ea = *(const float2*)&eattr[(size_t)ge0 * 128 + col];
                    float2 o = make_float2(c[mt][nt][0] + bv.x + ea.x,
                                           c[mt][nt][1] + bv.y + ea.y);
                    *(float2*)&out[(size_t)ge0 * 128 + col] = o;
                }
                if (ge1 < E) {
                    float2 ea = *(const float2*)&eattr[(size_t)ge1 * 128 + col];
                    float2 o = make_float2(c[mt][nt][2] + bv.x + ea.x,
                                           c[mt][nt][3] + bv.y + ea.y);
                    *(float2*)&out[(size_t)ge1 * 128 + col] = o;
                }
            }
        }
        __syncthreads();   // ps reused next batch
    }
}

// dual_out[i] = (idx==E) ? ones : edge_attr_new[idx]
__global__ void dual_gather(const int* __restrict__ idx, int M, int E,
                            const float* __restrict__ ea, float* __restrict__ out) {
    int tid = blockIdx.x * blockDim.x + threadIdx.x;
    if (tid >= M * 32) return;
    int i = tid >> 5, l = tid & 31;
    int id = idx[i];
    float4 v;
    if (id >= E) v = make_float4(1.f, 1.f, 1.f, 1.f);
    else         v = *(const float4*)&ea[(size_t)id * 128 + l * 4];
    *(float4*)&out[(size_t)i * 128 + l * 4] = v;
}

// ---------------- host orchestration ------------------------------------------

static const int MLP_SMEM = (256 * 136 + 64 * 260 + 256 + 256 + 128) * 4;  // ~204 KB

extern "C" void kernel_launch(void* const* d_in, const int* in_sizes, int n_in,
                              void* d_out, int out_size) {
    const float* x         = (const float*)d_in[0];
    const int*   ei[4]     = {(const int*)d_in[1], (const int*)d_in[2],
                              (const int*)d_in[3], (const int*)d_in[4]};
    const float* dual_attr = (const float*)d_in[5];
    const float* edge_attr = (const float*)d_in[6];
    const int*   oemap     = (const int*)d_in[7];

    const float *Wl[4], *Wr[4], *att[4], *bb[4];
    int p = 8;
    for (int c = 0; c < 4; c++) {
        Wl[c]  = (const float*)d_in[p++];
        Wr[c]  = (const float*)d_in[p++];
        att[c] = (const float*)d_in[p++];
        bb[c]  = (const float*)d_in[p++];
    }
    const float* We1    = (const float*)d_in[24];
    const float* fuse_W = (const float*)d_in[25];
    const float* fuse_b = (const float*)d_in[26];
    const float* ln_g   = (const float*)d_in[27];
    const float* ln_b   = (const float*)d_in[28];
    const float* mlp_W  = (const float*)d_in[29];
    const float* mlp_b  = (const float*)d_in[30];

    const int N     = in_sizes[0] / 128;
    const int Ec[4] = {in_sizes[1] / 2, in_sizes[2] / 2, in_sizes[3] / 2, in_sizes[4] / 2};
    const int M_oe  = in_sizes[7];
    const int E1    = Ec[0];

    float *xlr, *wcat, *xcat, *elog, *nmax, *nsum, *pre;
    cudaGetSymbolAddress((void**)&xlr,  g_xlr);
    cudaGetSymbolAddress((void**)&wcat, g_wcat);
    cudaGetSymbolAddress((void**)&xcat, g_xcat);
    cudaGetSymbolAddress((void**)&elog, g_elog);
    cudaGetSymbolAddress((void**)&nmax, g_nmax);
    cudaGetSymbolAddress((void**)&nsum, g_nsum);
    cudaGetSymbolAddress((void**)&pre,  g_pre);

    cudaFuncSetAttribute(edge_mlp, cudaFuncAttributeMaxDynamicSharedMemorySize, MLP_SMEM);

    // pack (Wl|Wr) x 4 -> wcat [128,1024]
    pack_w<<<(128 * 1024 + 255) / 256, 256>>>(Wl[0], Wr[0], Wl[1], Wr[1],
                                              Wl[2], Wr[2], Wl[3], Wr[3], wcat);

    // pre = dual_attr @ We1
    {
        dim3 grid((E1 + 127) / 128, 1);
        gemm_mma<128, 128, 128><<<grid, 256>>>(dual_attr, We1, nullptr, pre, E1);
    }

    // one wide GEMM for all 8 node projections: xlr = x @ wcat
    {
        dim3 grid((N + 127) / 128, 8);
        gemm_mma<128, 1024, 1024><<<grid, 256>>>(x, wcat, nullptr, xlr, N);
    }

    init_xcat<<<(N * 128 + 255) / 256, 256>>>(xcat, bb[0], bb[1], bb[2], bb[3], N);

    for (int c = 0; c < 4; c++) {
        const int E = Ec[c];
        const int* src = ei[c];
        const int* dst = ei[c] + E;
        const int cofs = c * 256;

        init_ns<<<(N * 16 + 255) / 256, 256>>>(nmax, nsum, N * 16);

        if (c == 0)
            edge_logits<true><<<(E + 7) / 8, 256>>>(src, dst, E, xlr, cofs, pre,
                                                    att[c], elog, nmax);
        else
            edge_logits<false><<<(E + 7) / 8, 256>>>(src, dst, E, xlr, cofs, nullptr,
                                                     att[c], elog, nmax);

        edge_exp<<<(E * 4 + 255) / 256, 256>>>(dst, E, nmax, elog, nsum);
        edge_agg<<<(E + 7) / 8, 256>>>(src, dst, E, elog, nsum, xlr, cofs,
                                       xcat, c * 128);
    }

    // fuse: xf = xcat @ fuse_W + fuse_b  -> output section 0
    float* xf = (float*)d_out;
    {
        dim3 grid((N + 127) / 128, 1);
        gemm_mma<512, 128, 128><<<grid, 256>>>(xcat, fuse_W, fuse_b, xf, N);
    }

    // edge MLP -> output section 1 (persistent, tensor-core batch matvec)
    float* eout = (float*)d_out + (size_t)N * 128;
    edge_mlp<<<148, 512, MLP_SMEM>>>(ei[0], ei[0] + E1, E1, xf, ln_g, ln_b,
                                     mlp_W, mlp_b, edge_attr, eout);

    // dual gather -> output section 2
    float* dout = eout + (size_t)E1 * 128;
    dual_gather<<<(M_oe * 32 + 255) / 256, 256>>>(oemap, M_oe, E1, eout, dout);
}

// round 13
// speedup vs baseline: 21.2667x; 1.1729x over previous
#include <cuda_runtime.h>
#include <cstdint>

// ---------------- scratch (device globals; no allocation allowed) -------------
#define MAXN 50000
#define MAXE 500000

__device__ float g_xlr[(size_t)MAXN * 1024];  // [N][8*128]: (Wl|Wr) x 4 convs
__device__ float g_wcat[128 * 1024];          // packed weights [k][1024]
__device__ float g_xcat[MAXN * 512];
__device__ float g_nsum[4 * MAXN * 16];       // per-conv segment sums
__device__ float g_pre[(size_t)MAXE * 128];   // dual_attr @ We1

// ---------------- helpers -----------------------------------------------------

__device__ __forceinline__ uint32_t tf32u(float x) {
    uint32_t u; asm("cvt.rna.tf32.f32 %0, %1;" : "=r"(u) : "f"(x)); return u;
}
__device__ __forceinline__ float4 tf32cvt4(float4 v) {
    float4 r;
    r.x = __uint_as_float(tf32u(v.x));
    r.y = __uint_as_float(tf32u(v.y));
    r.z = __uint_as_float(tf32u(v.z));
    r.w = __uint_as_float(tf32u(v.w));
    return r;
}
__device__ __forceinline__ void mma_tf32(float* c, const uint32_t* a, const uint32_t* b) {
    asm volatile(
        "mma.sync.aligned.m16n8k8.row.col.f32.tf32.tf32.f32 "
        "{%0,%1,%2,%3}, {%4,%5,%6,%7}, {%8,%9}, {%0,%1,%2,%3};\n"
        : "+f"(c[0]), "+f"(c[1]), "+f"(c[2]), "+f"(c[3])
        : "r"(a[0]), "r"(a[1]), "r"(a[2]), "r"(a[3]), "r"(b[0]), "r"(b[1]));
}

// pack 8 [128,128] weight mats into wcat[k][w*128+j]
__global__ void pack_w(const float* __restrict__ w0, const float* __restrict__ w1,
                       const float* __restrict__ w2, const float* __restrict__ w3,
                       const float* __restrict__ w4, const float* __restrict__ w5,
                       const float* __restrict__ w6, const float* __restrict__ w7,
                       float* __restrict__ wcat) {
    int idx = blockIdx.x * blockDim.x + threadIdx.x;
    if (idx >= 128 * 1024) return;
    int w = (idx >> 14), rem = idx & 16383;
    int k = rem >> 7, j = rem & 127;
    const float* ws[8] = {w0, w1, w2, w3, w4, w5, w6, w7};
    wcat[k * 1024 + w * 128 + j] = ws[w][k * 128 + j];
}

// ---------------- tf32 tensor-core GEMM: out[M,NW] = A[M,K] @ W[K,NW] (+bias)
template <int K, int NW, int OSTRIDE>
__global__ __launch_bounds__(256)
void gemm_mma(const float* __restrict__ A, const float* __restrict__ W,
              const float* __restrict__ bias, float* __restrict__ out, int M) {
    __shared__ float As[128][36];   // [m][k]
    __shared__ float Ws[32][136];   // [k][n]

    const int tid = threadIdx.x;
    const int l = tid & 31, w = tid >> 5;
    const int g = l >> 2, tg = l & 3;
    const int wm = (w & 3) * 32;
    const int wn = (w >> 2) * 64;
    const int r0 = blockIdx.x * 128;
    const int c0 = blockIdx.y * 128;

    float c[2][8][4];
#pragma unroll
    for (int mt = 0; mt < 2; mt++)
#pragma unroll
        for (int nt = 0; nt < 8; nt++)
#pragma unroll
            for (int i = 0; i < 4; i++) c[mt][nt][i] = 0.f;

    for (int kt = 0; kt < K; kt += 32) {
#pragma unroll
        for (int i = 0; i < 4; i++) {
            int flat = tid + i * 256;
            int r = flat >> 3, kq = flat & 7;
            float4 v = (r0 + r < M)
                ? *(const float4*)&A[(size_t)(r0 + r) * K + kt + kq * 4]
                : make_float4(0.f, 0.f, 0.f, 0.f);
            *(float4*)&As[r][kq * 4] = tf32cvt4(v);
        }
#pragma unroll
        for (int i = 0; i < 4; i++) {
            int flat = tid + i * 256;
            int k = flat >> 5, n4 = flat & 31;
            float4 v = *(const float4*)&W[(size_t)(kt + k) * NW + c0 + n4 * 4];
            *(float4*)&Ws[k][n4 * 4] = tf32cvt4(v);
        }
        __syncthreads();

#pragma unroll
        for (int k8 = 0; k8 < 4; k8++) {
            const int kb = k8 * 8;
            uint32_t a[2][4], b[8][2];
#pragma unroll
            for (int mt = 0; mt < 2; mt++) {
                int m = wm + mt * 16;
                a[mt][0] = __float_as_uint(As[m + g][kb + tg]);
                a[mt][1] = __float_as_uint(As[m + 8 + g][kb + tg]);
                a[mt][2] = __float_as_uint(As[m + g][kb + tg + 4]);
                a[mt][3] = __float_as_uint(As[m + 8 + g][kb + tg + 4]);
            }
#pragma unroll
            for (int nt = 0; nt < 8; nt++) {
                int n = wn + nt * 8;
                b[nt][0] = __float_as_uint(Ws[kb + tg][n + g]);
                b[nt][1] = __float_as_uint(Ws[kb + tg + 4][n + g]);
            }
#pragma unroll
            for (int mt = 0; mt < 2; mt++)
#pragma unroll
                for (int nt = 0; nt < 8; nt++)
                    mma_tf32(c[mt][nt], a[mt], b[nt]);
        }
        __syncthreads();
    }

#pragma unroll
    for (int mt = 0; mt < 2; mt++) {
#pragma unroll
        for (int nt = 0; nt < 8; nt++) {
            int row = r0 + wm + mt * 16 + g;
            int col = c0 + wn + nt * 8 + tg * 2;
            float2 bv = bias ? *(const float2*)&bias[col] : make_float2(0.f, 0.f);
            if (row < M) {
                float2 o = make_float2(c[mt][nt][0] + bv.x, c[mt][nt][1] + bv.y);
                *(float2*)&out[(size_t)row * OSTRIDE + col] = o;
            }
            if (row + 8 < M) {
                float2 o = make_float2(c[mt][nt][2] + bv.x, c[mt][nt][3] + bv.y);
                *(float2*)&out[(size_t)(row + 8) * OSTRIDE + col] = o;
            }
        }
    }
}

// ---------------- single fused edge pass ---------------------------------------
// Per edge (1 warp slot of 32 lanes): gather xl[s], xr[d] (+pre), per-head logit,
// e = exp(logit) (no max subtraction: |logit| < ~5, safe; the softmax ratio is
// invariant), RED e into nsum, RED e*xl[s] into xcat (unnormalized).
template <bool HASE>
__global__ void edge_fused(const int* __restrict__ src, const int* __restrict__ dst, int E,
                           const float* __restrict__ xlr, int cofs,
                           const float* __restrict__ pre,
                           const float* __restrict__ att,
                           float* __restrict__ nsum, float* __restrict__ xcat, int xofs) {
    const int l = threadIdx.x & 31;
    const int slot = threadIdx.x >> 5;
    const int e = blockIdx.x * 8 + slot;
    if (e >= E) return;
    int s = src[e], d = dst[e];
    float4 a = *(const float4*)&xlr[(size_t)s * 1024 + cofs + l * 4];        // xl[s]
    float4 b = *(const float4*)&xlr[(size_t)d * 1024 + cofs + 128 + l * 4];  // xr[d]
    float4 m = make_float4(a.x + b.x, a.y + b.y, a.z + b.z, a.w + b.w);
    if (HASE) {
        float4 p = *(const float4*)&pre[(size_t)e * 128 + l * 4];
        m.x += p.x; m.y += p.y; m.z += p.z; m.w += p.w;
    }
    float4 t4 = *(const float4*)&att[l * 4];
    float lx = (m.x > 0.f) ? m.x : 0.2f * m.x;
    float ly = (m.y > 0.f) ? m.y : 0.2f * m.y;
    float lz = (m.z > 0.f) ? m.z : 0.2f * m.z;
    float lw = (m.w > 0.f) ? m.w : 0.2f * m.w;
    float partial = lx * t4.x + ly * t4.y + lz * t4.z + lw * t4.w;
    partial += __shfl_xor_sync(0xffffffffu, partial, 1);   // full logit for head l>>1

    float ev = __expf(partial);

    if ((l & 1) == 0) {
        float* pn = &nsum[(size_t)d * 16 + (l >> 1)];
        asm volatile("red.global.add.f32 [%0], %1;" :: "l"(pn), "f"(ev) : "memory");
    }

    float* p = &xcat[(size_t)d * 512 + xofs + l * 4];
    asm volatile("red.global.add.v4.f32 [%0], {%1,%2,%3,%4};" ::
                 "l"(p), "f"(ev * a.x), "f"(ev * a.y),
                 "f"(ev * a.z), "f"(ev * a.w) : "memory");
}

// finalize: xcat[n, c*128+j] = b_c[j] + xcat / (nsum[c][n,h] + 1e-16)
__global__ void finalize_xcat(float* __restrict__ xcat, const float* __restrict__ nsum,
                              const float* __restrict__ b1, const float* __restrict__ b2,
                              const float* __restrict__ b3, const float* __restrict__ b4,
                              int N) {
    int idx = blockIdx.x * blockDim.x + threadIdx.x;   // over N*128 float4s
    if (idx >= N * 128) return;
    int n = idx >> 7, col4 = idx & 127;
    int c = col4 >> 5, j4 = col4 & 31;
    int h = j4 >> 1;                                   // features j4*4..+3 share head
    const float* b = (c == 0) ? b1 : (c == 1) ? b2 : (c == 2) ? b3 : b4;
    float inv = 1.f / (nsum[((size_t)c * MAXN + n) * 16 + h] + 1e-16f);
    float4 v = *(float4*)&xcat[(size_t)idx * 4];
    float4 bv = *(const float4*)&b[j4 * 4];
    v.x = bv.x + v.x * inv;
    v.y = bv.y + v.y * inv;
    v.z = bv.z + v.z * inv;
    v.w = bv.w + v.w * inv;
    *(float4*)&xcat[(size_t)idx * 4] = v;
}

// ---------------- persistent edge MLP (tensor-core matvec batch) ---------------
__global__ __launch_bounds__(512, 1)
void edge_mlp(const int* __restrict__ src, const int* __restrict__ dst, int E,
              const float* __restrict__ xf,
              const float* __restrict__ lng, const float* __restrict__ lnb,
              const float* __restrict__ W, const float* __restrict__ mlpb,
              const float* __restrict__ eattr, float* __restrict__ out) {
    extern __shared__ float sm[];
    float (*Wks)[136] = (float(*)[136])sm;                 // 256*136
    float (*ps)[260]  = (float(*)[260])(sm + 256 * 136);   // 64*260
    float* lg = sm + 256 * 136 + 64 * 260;                 // 256
    float* lb = lg + 256;                                  // 256
    float* mb = lb + 256;                                  // 128

    const int tid = threadIdx.x;
    const int l = tid & 31, w = tid >> 5;
    const int g = l >> 2, tg = l & 3;
    const int wm = (w & 1) * 32;     // 2 m-warps
    const int wn = (w >> 1) * 16;    // 8 n-warps x 16 cols

#pragma unroll
    for (int i = 0; i < 16; i++) {
        int flat = tid + i * 512;
        int k = flat >> 5, n4 = flat & 31;
        float4 v = *(const float4*)&W[(size_t)k * 128 + n4 * 4];
        *(float4*)&Wks[k][n4 * 4] = tf32cvt4(v);
    }
    if (tid < 256) { lg[tid] = lng[tid]; lb[tid] = lnb[tid]; }
    if (tid < 128) mb[tid] = mlpb[tid];
    __syncthreads();

    for (int base = blockIdx.x * 64; base < E; base += gridDim.x * 64) {
#pragma unroll
        for (int e = 0; e < 4; e++) {
            int le = w * 4 + e;
            int ge = base + le;
            float4 ra, rb;
            if (ge < E) {
                int s = src[ge], d = dst[ge];
                float4 a = *(const float4*)&xf[(size_t)s * 128 + l * 4];
                float4 b = *(const float4*)&xf[(size_t)d * 128 + l * 4];
                float sum = a.x + a.y + a.z + a.w + b.x + b.y + b.z + b.w;
                float sq  = a.x * a.x + a.y * a.y + a.z * a.z + a.w * a.w
                          + b.x * b.x + b.y * b.y + b.z * b.z + b.w * b.w;
#pragma unroll
                for (int off = 16; off; off >>= 1) {
                    sum += __shfl_xor_sync(0xffffffffu, sum, off);
                    sq  += __shfl_xor_sync(0xffffffffu, sq, off);
                }
                float mu = sum * (1.f / 256.f);
                float var = sq * (1.f / 256.f) - mu * mu;
                float rs = rsqrtf(var + 1e-5f);
                float4 ga = *(const float4*)&lg[l * 4];
                float4 ba = *(const float4*)&lb[l * 4];
                float4 gb = *(const float4*)&lg[128 + l * 4];
                float4 bb = *(const float4*)&lb[128 + l * 4];
                ra.x = fmaxf(0.f, (a.x - mu) * rs * ga.x + ba.x);
                ra.y = fmaxf(0.f, (a.y - mu) * rs * ga.y + ba.y);
                ra.z = fmaxf(0.f, (a.z - mu) * rs * ga.z + ba.z);
                ra.w = fmaxf(0.f, (a.w - mu) * rs * ga.w + ba.w);
                rb.x = fmaxf(0.f, (b.x - mu) * rs * gb.x + bb.x);
                rb.y = fmaxf(0.f, (b.y - mu) * rs * gb.y + bb.y);
                rb.z = fmaxf(0.f, (b.z - mu) * rs * gb.z + bb.z);
                rb.w = fmaxf(0.f, (b.w - mu) * rs * gb.w + bb.w);
            } else {
                ra = rb = make_float4(0.f, 0.f, 0.f, 0.f);
            }
            *(float4*)&ps[le][l * 4]       = tf32cvt4(ra);
            *(float4*)&ps[le][128 + l * 4] = tf32cvt4(rb);
        }
        __syncthreads();

        float c[2][2][4];
#pragma unroll
        for (int mt = 0; mt < 2; mt++)
#pragma unroll
            for (int nt = 0; nt < 2; nt++)
#pragma unroll
                for (int i = 0; i < 4; i++) c[mt][nt][i] = 0.f;

#pragma unroll 4
        for (int k8 = 0; k8 < 32; k8++) {
            const int kb = k8 * 8;
            uint32_t a[2][4], b[2][2];
#pragma unroll
            for (int mt = 0; mt < 2; mt++) {
                int m = wm + mt * 16;
                a[mt][0] = __float_as_uint(ps[m + g][kb + tg]);
                a[mt][1] = __float_as_uint(ps[m + 8 + g][kb + tg]);
                a[mt][2] = __float_as_uint(ps[m + g][kb + tg + 4]);
                a[mt][3] = __float_as_uint(ps[m + 8 + g][kb + tg + 4]);
            }
#pragma unroll
            for (int nt = 0; nt < 2; nt++) {
                int n = wn + nt * 8;
                b[nt][0] = __float_as_uint(Wks[kb + tg][n + g]);
                b[nt][1] = __float_as_uint(Wks[kb + tg + 4][n + g]);
            }
#pragma unroll
            for (int mt = 0; mt < 2; mt++)
#pragma unroll
                for (int nt = 0; nt < 2; nt++)
                    mma_tf32(c[mt][nt], a[mt], b[nt]);
        }

#pragma unroll
        for (int mt = 0; mt < 2; mt++) {
#pragma unroll
            for (int nt = 0; nt < 2; nt++) {
                int le = wm + mt * 16 + g;
                int col = wn + nt * 8 + tg * 2;
                float2 bv = *(const float2*)&mb[col];
                int ge0 = base + le;
                int ge1 = ge0 + 8;
                if (ge0 < E) {
                    float2 ea = *(const float2*)&eattr[(size_t)ge0 * 128 + col];
                    float2 o = make_float2(c[mt][nt][0] + bv.x + ea.x,
                                           c[mt][nt][1] + bv.y + ea.y);
                    *(float2*)&out[(size_t)ge0 * 128 + col] = o;
                }
                if (ge1 < E) {
                    float2 ea = *(const float2*)&eattr[(size_t)ge1 * 128 + col];
                    float2 o = make_float2(c[mt][nt][2] + bv.x + ea.x,
                                           c[mt][nt][3] + bv.y + ea.y);
                    *(float2*)&out[(size_t)ge1 * 128 + col] = o;
                }
            }
        }
        __syncthreads();   // ps reused next batch
    }
}

// dual_out[i] = (idx==E) ? ones : edge_attr_new[idx]
__global__ void dual_gather(const int* __restrict__ idx, int M, int E,
                            const float* __restrict__ ea, float* __restrict__ out) {
    int tid = blockIdx.x * blockDim.x + threadIdx.x;
    if (tid >= M * 32) return;
    int i = tid >> 5, l = tid & 31;
    int id = idx[i];
    float4 v;
    if (id >= E) v = make_float4(1.f, 1.f, 1.f, 1.f);
    else         v = *(const float4*)&ea[(size_t)id * 128 + l * 4];
    *(float4*)&out[(size_t)i * 128 + l * 4] = v;
}

// ---------------- host orchestration ------------------------------------------

static const int MLP_SMEM = (256 * 136 + 64 * 260 + 256 + 256 + 128) * 4;  // ~204 KB

extern "C" void kernel_launch(void* const* d_in, const int* in_sizes, int n_in,
                              void* d_out, int out_size) {
    const float* x         = (const float*)d_in[0];
    const int*   ei[4]     = {(const int*)d_in[1], (const int*)d_in[2],
                              (const int*)d_in[3], (const int*)d_in[4]};
    const float* dual_attr = (const float*)d_in[5];
    const float* edge_attr = (const float*)d_in[6];
    const int*   oemap     = (const int*)d_in[7];

    const float *Wl[4], *Wr[4], *att[4], *bb[4];
    int p = 8;
    for (int c = 0; c < 4; c++) {
        Wl[c]  = (const float*)d_in[p++];
        Wr[c]  = (const float*)d_in[p++];
        att[c] = (const float*)d_in[p++];
        bb[c]  = (const float*)d_in[p++];
    }
    const float* We1    = (const float*)d_in[24];
    const float* fuse_W = (const float*)d_in[25];
    const float* fuse_b = (const float*)d_in[26];
    const float* ln_g   = (const float*)d_in[27];
    const float* ln_b   = (const float*)d_in[28];
    const float* mlp_W  = (const float*)d_in[29];
    const float* mlp_b  = (const float*)d_in[30];

    const int N     = in_sizes[0] / 128;
    const int Ec[4] = {in_sizes[1] / 2, in_sizes[2] / 2, in_sizes[3] / 2, in_sizes[4] / 2};
    const int M_oe  = in_sizes[7];
    const int E1    = Ec[0];

    float *xlr, *wcat, *xcat, *nsum, *pre;
    cudaGetSymbolAddress((void**)&xlr,  g_xlr);
    cudaGetSymbolAddress((void**)&wcat, g_wcat);
    cudaGetSymbolAddress((void**)&xcat, g_xcat);
    cudaGetSymbolAddress((void**)&nsum, g_nsum);
    cudaGetSymbolAddress((void**)&pre,  g_pre);

    cudaFuncSetAttribute(edge_mlp, cudaFuncAttributeMaxDynamicSharedMemorySize, MLP_SMEM);

    // zero accumulators (graph-capturable async memsets)
    cudaMemsetAsync(xcat, 0, (size_t)N * 512 * sizeof(float), 0);
    cudaMemsetAsync(nsum, 0, (size_t)4 * MAXN * 16 * sizeof(float), 0);

    // pack (Wl|Wr) x 4 -> wcat [128,1024]
    pack_w<<<(128 * 1024 + 255) / 256, 256>>>(Wl[0], Wr[0], Wl[1], Wr[1],
                                              Wl[2], Wr[2], Wl[3], Wr[3], wcat);

    // pre = dual_attr @ We1
    {
        dim3 grid((E1 + 127) / 128, 1);
        gemm_mma<128, 128, 128><<<grid, 256>>>(dual_attr, We1, nullptr, pre, E1);
    }

    // one wide GEMM for all 8 node projections: xlr = x @ wcat
    {
        dim3 grid((N + 127) / 128, 8);
        gemm_mma<128, 1024, 1024><<<grid, 256>>>(x, wcat, nullptr, xlr, N);
    }

    // single fused edge pass per conv (unnormalized scatter + segment sums)
    for (int c = 0; c < 4; c++) {
        const int E = Ec[c];
        const int* src = ei[c];
        const int* dst = ei[c] + E;
        float* nsum_c = nsum + (size_t)c * MAXN * 16;

        if (c == 0)
            edge_fused<true><<<(E + 7) / 8, 256>>>(src, dst, E, xlr, 0, pre,
                                                   att[0], nsum_c, xcat, 0);
        else
            edge_fused<false><<<(E + 7) / 8, 256>>>(src, dst, E, xlr, c * 256, nullptr,
                                                    att[c], nsum_c, xcat, c * 128);
    }

    // normalize + bias
    finalize_xcat<<<(N * 128 + 255) / 256, 256>>>(xcat, nsum,
                                                  bb[0], bb[1], bb[2], bb[3], N);

    // fuse: xf = xcat @ fuse_W + fuse_b  -> output section 0
    float* xf = (float*)d_out;
    {
        dim3 grid((N + 127) / 128, 1);
        gemm_mma<512, 128, 128><<<grid, 256>>>(xcat, fuse_W, fuse_b, xf, N);
    }

    // edge MLP -> output section 1 (persistent, tensor-core batch matvec)
    float* eout = (float*)d_out + (size_t)N * 128;
    edge_mlp<<<148, 512, MLP_SMEM>>>(ei[0], ei[0] + E1, E1, xf, ln_g, ln_b,
                                     mlp_W, mlp_b, edge_attr, eout);

    // dual gather -> output section 2
    float* dout = eout + (size_t)E1 * 128;
    dual_gather<<<(M_oe * 32 + 255) / 256, 256>>>(oemap, M_oe, E1, eout, dout);
}

// round 15
// speedup vs baseline: 21.2870x; 1.0010x over previous
#include <cuda_runtime.h>
#include <cstdint>

// ---------------- scratch (device globals; no allocation allowed) -------------
#define MAXN 50000
#define MAXE 500000

__device__ float g_xlr[(size_t)MAXN * 1024];  // [N][8*128]: (Wl|Wr) x 4 convs
__device__ float g_wcat[128 * 1024];          // packed weights [k][1024]
__device__ float g_xcat[MAXN * 512];
__device__ float g_nsum[4 * MAXN * 16];       // per-conv segment sums

// ---------------- helpers -----------------------------------------------------

__device__ __forceinline__ uint32_t tf32u(float x) {
    uint32_t u; asm("cvt.rna.tf32.f32 %0, %1;" : "=r"(u) : "f"(x)); return u;
}
__device__ __forceinline__ float4 tf32cvt4(float4 v) {
    float4 r;
    r.x = __uint_as_float(tf32u(v.x));
    r.y = __uint_as_float(tf32u(v.y));
    r.z = __uint_as_float(tf32u(v.z));
    r.w = __uint_as_float(tf32u(v.w));
    return r;
}
__device__ __forceinline__ void mma_tf32(float* c, const uint32_t* a, const uint32_t* b) {
    asm volatile(
        "mma.sync.aligned.m16n8k8.row.col.f32.tf32.tf32.f32 "
        "{%0,%1,%2,%3}, {%4,%5,%6,%7}, {%8,%9}, {%0,%1,%2,%3};\n"
        : "+f"(c[0]), "+f"(c[1]), "+f"(c[2]), "+f"(c[3])
        : "r"(a[0]), "r"(a[1]), "r"(a[2]), "r"(a[3]), "r"(b[0]), "r"(b[1]));
}

// pack 8 [128,128] weight mats into wcat[k][w*128+j]
__global__ void pack_w(const float* __restrict__ w0, const float* __restrict__ w1,
                       const float* __restrict__ w2, const float* __restrict__ w3,
                       const float* __restrict__ w4, const float* __restrict__ w5,
                       const float* __restrict__ w6, const float* __restrict__ w7,
                       float* __restrict__ wcat) {
    int idx = blockIdx.x * blockDim.x + threadIdx.x;
    if (idx >= 128 * 1024) return;
    int w = (idx >> 14), rem = idx & 16383;
    int k = rem >> 7, j = rem & 127;
    const float* ws[8] = {w0, w1, w2, w3, w4, w5, w6, w7};
    wcat[k * 1024 + w * 128 + j] = ws[w][k * 128 + j];
}

// ---------------- tf32 tensor-core GEMM: out[M,NW] = A[M,K] @ W[K,NW] (+bias)
template <int K, int NW, int OSTRIDE>
__global__ __launch_bounds__(256)
void gemm_mma(const float* __restrict__ A, const float* __restrict__ W,
              const float* __restrict__ bias, float* __restrict__ out, int M) {
    __shared__ float As[128][36];   // [m][k]
    __shared__ float Ws[32][136];   // [k][n]

    const int tid = threadIdx.x;
    const int l = tid & 31, w = tid >> 5;
    const int g = l >> 2, tg = l & 3;
    const int wm = (w & 3) * 32;
    const int wn = (w >> 2) * 64;
    const int r0 = blockIdx.x * 128;
    const int c0 = blockIdx.y * 128;

    float c[2][8][4];
#pragma unroll
    for (int mt = 0; mt < 2; mt++)
#pragma unroll
        for (int nt = 0; nt < 8; nt++)
#pragma unroll
            for (int i = 0; i < 4; i++) c[mt][nt][i] = 0.f;

    for (int kt = 0; kt < K; kt += 32) {
#pragma unroll
        for (int i = 0; i < 4; i++) {
            int flat = tid + i * 256;
            int r = flat >> 3, kq = flat & 7;
            float4 v = (r0 + r < M)
                ? *(const float4*)&A[(size_t)(r0 + r) * K + kt + kq * 4]
                : make_float4(0.f, 0.f, 0.f, 0.f);
            *(float4*)&As[r][kq * 4] = tf32cvt4(v);
        }
#pragma unroll
        for (int i = 0; i < 4; i++) {
            int flat = tid + i * 256;
            int k = flat >> 5, n4 = flat & 31;
            float4 v = *(const float4*)&W[(size_t)(kt + k) * NW + c0 + n4 * 4];
            *(float4*)&Ws[k][n4 * 4] = tf32cvt4(v);
        }
        __syncthreads();

#pragma unroll
        for (int k8 = 0; k8 < 4; k8++) {
            const int kb = k8 * 8;
            uint32_t a[2][4], b[8][2];
#pragma unroll
            for (int mt = 0; mt < 2; mt++) {
                int m = wm + mt * 16;
                a[mt][0] = __float_as_uint(As[m + g][kb + tg]);
                a[mt][1] = __float_as_uint(As[m + 8 + g][kb + tg]);
                a[mt][2] = __float_as_uint(As[m + g][kb + tg + 4]);
                a[mt][3] = __float_as_uint(As[m + 8 + g][kb + tg + 4]);
            }
#pragma unroll
            for (int nt = 0; nt < 8; nt++) {
                int n = wn + nt * 8;
                b[nt][0] = __float_as_uint(Ws[kb + tg][n + g]);
                b[nt][1] = __float_as_uint(Ws[kb + tg + 4][n + g]);
            }
#pragma unroll
            for (int mt = 0; mt < 2; mt++)
#pragma unroll
                for (int nt = 0; nt < 8; nt++)
                    mma_tf32(c[mt][nt], a[mt], b[nt]);
        }
        __syncthreads();
    }

#pragma unroll
    for (int mt = 0; mt < 2; mt++) {
#pragma unroll
        for (int nt = 0; nt < 8; nt++) {
            int row = r0 + wm + mt * 16 + g;
            int col = c0 + wn + nt * 8 + tg * 2;
            float2 bv = bias ? *(const float2*)&bias[col] : make_float2(0.f, 0.f);
            if (row < M) {
                float2 o = make_float2(c[mt][nt][0] + bv.x, c[mt][nt][1] + bv.y);
                *(float2*)&out[(size_t)row * OSTRIDE + col] = o;
            }
            if (row + 8 < M) {
                float2 o = make_float2(c[mt][nt][2] + bv.x, c[mt][nt][3] + bv.y);
                *(float2*)&out[(size_t)(row + 8) * OSTRIDE + col] = o;
            }
        }
    }
}

// ---------------- conv0: fused (dual_attr @ We1) GEMM + edge softmax pass ------
// One block per 128-edge tile. Phase 1: tf32 MMA computes pre[128][128] in
// fragments (never hits global). Phase 2: fragments -> smem (union over dead
// As/Ws staging). Phase 3: each warp processes 16 edges: pre row from smem +
// xl/xr gathers -> logit -> exp -> RED scatters.
__global__ __launch_bounds__(256)
void edge_conv0(const float* __restrict__ A /*dual_attr*/, const float* __restrict__ W /*We1*/,
                const int* __restrict__ src, const int* __restrict__ dst, int E,
                const float* __restrict__ xlr, const float* __restrict__ att,
                float* __restrict__ nsum, float* __restrict__ xcat) {
    __shared__ float smu[128 * 136];            // union: phase1 As+Ws | phase3 pre_s
    float (*As)[36]   = (float(*)[36])smu;                    // 128*36 = 4608
    float (*Ws)[136]  = (float(*)[136])(smu + 128 * 36);      // 32*136 = 4352
    float (*pre_s)[136] = (float(*)[136])smu;                 // 128*136

    const int tid = threadIdx.x;
    const int l = tid & 31, w = tid >> 5;
    const int g = l >> 2, tg = l & 3;
    const int wm = (w & 3) * 32;
    const int wn = (w >> 2) * 64;
    const int r0 = blockIdx.x * 128;            // first edge of tile

    float c[2][8][4];
#pragma unroll
    for (int mt = 0; mt < 2; mt++)
#pragma unroll
        for (int nt = 0; nt < 8; nt++)
#pragma unroll
            for (int i = 0; i < 4; i++) c[mt][nt][i] = 0.f;

    for (int kt = 0; kt < 128; kt += 32) {
#pragma unroll
        for (int i = 0; i < 4; i++) {
            int flat = tid + i * 256;
            int r = flat >> 3, kq = flat & 7;
            float4 v = (r0 + r < E)
                ? *(const float4*)&A[(size_t)(r0 + r) * 128 + kt + kq * 4]
                : make_float4(0.f, 0.f, 0.f, 0.f);
            *(float4*)&As[r][kq * 4] = tf32cvt4(v);
        }
#pragma unroll
        for (int i = 0; i < 4; i++) {
            int flat = tid + i * 256;
            int k = flat >> 5, n4 = flat & 31;
            float4 v = *(const float4*)&W[(size_t)(kt + k) * 128 + n4 * 4];
            *(float4*)&Ws[k][n4 * 4] = tf32cvt4(v);
        }
        __syncthreads();

#pragma unroll
        for (int k8 = 0; k8 < 4; k8++) {
            const int kb = k8 * 8;
            uint32_t a[2][4], b[8][2];
#pragma unroll
            for (int mt = 0; mt < 2; mt++) {
                int m = wm + mt * 16;
                a[mt][0] = __float_as_uint(As[m + g][kb + tg]);
                a[mt][1] = __float_as_uint(As[m + 8 + g][kb + tg]);
                a[mt][2] = __float_as_uint(As[m + g][kb + tg + 4]);
                a[mt][3] = __float_as_uint(As[m + 8 + g][kb + tg + 4]);
            }
#pragma unroll
            for (int nt = 0; nt < 8; nt++) {
                int n = wn + nt * 8;
                b[nt][0] = __float_as_uint(Ws[kb + tg][n + g]);
                b[nt][1] = __float_as_uint(Ws[kb + tg + 4][n + g]);
            }
#pragma unroll
            for (int mt = 0; mt < 2; mt++)
#pragma unroll
                for (int nt = 0; nt < 8; nt++)
                    mma_tf32(c[mt][nt], a[mt], b[nt]);
        }
        __syncthreads();
    }

    // phase 2: fragments -> pre_s (As/Ws are dead after the last sync above)
#pragma unroll
    for (int mt = 0; mt < 2; mt++) {
#pragma unroll
        for (int nt = 0; nt < 8; nt++) {
            int lr = wm + mt * 16 + g;
            int col = wn + nt * 8 + tg * 2;
            *(float2*)&pre_s[lr][col]     = make_float2(c[mt][nt][0], c[mt][nt][1]);
            *(float2*)&pre_s[lr + 8][col] = make_float2(c[mt][nt][2], c[mt][nt][3]);
        }
    }
    __syncthreads();

    // phase 3: each warp handles 16 edges
#pragma unroll 4
    for (int i = 0; i < 16; i++) {
        int le = w * 16 + i;
        int e = r0 + le;
        if (e >= E) break;
        int s = src[e], d = dst[e];
        float4 a = *(const float4*)&xlr[(size_t)s * 1024 + l * 4];        // xl[s], conv0
        float4 b = *(const float4*)&xlr[(size_t)d * 1024 + 128 + l * 4];  // xr[d], conv0
        float4 p = *(const float4*)&pre_s[le][l * 4];
        float4 m = make_float4(a.x + b.x + p.x, a.y + b.y + p.y,
                               a.z + b.z + p.z, a.w + b.w + p.w);
        float4 t4 = *(const float4*)&att[l * 4];
        float lx = (m.x > 0.f) ? m.x : 0.2f * m.x;
        float ly = (m.y > 0.f) ? m.y : 0.2f * m.y;
        float lz = (m.z > 0.f) ? m.z : 0.2f * m.z;
        float lw = (m.w > 0.f) ? m.w : 0.2f * m.w;
        float partial = lx * t4.x + ly * t4.y + lz * t4.z + lw * t4.w;
        partial += __shfl_xor_sync(0xffffffffu, partial, 1);
        float ev = __expf(partial);

        if ((l & 1) == 0) {
            float* pn = &nsum[(size_t)d * 16 + (l >> 1)];
            asm volatile("red.global.add.f32 [%0], %1;" :: "l"(pn), "f"(ev) : "memory");
        }
        float* pp = &xcat[(size_t)d * 512 + l * 4];
        asm volatile("red.global.add.v4.f32 [%0], {%1,%2,%3,%4};" ::
                     "l"(pp), "f"(ev * a.x), "f"(ev * a.y),
                     "f"(ev * a.z), "f"(ev * a.w) : "memory");
    }
}

// ---------------- fused edge pass for convs without edge attrs -----------------
__global__ void edge_fused(const int* __restrict__ src, const int* __restrict__ dst, int E,
                           const float* __restrict__ xlr, int cofs,
                           const float* __restrict__ att,
                           float* __restrict__ nsum, float* __restrict__ xcat, int xofs) {
    const int l = threadIdx.x & 31;
    const int slot = threadIdx.x >> 5;
    const int e = blockIdx.x * 8 + slot;
    if (e >= E) return;
    int s = src[e], d = dst[e];
    float4 a = *(const float4*)&xlr[(size_t)s * 1024 + cofs + l * 4];        // xl[s]
    float4 b = *(const float4*)&xlr[(size_t)d * 1024 + cofs + 128 + l * 4];  // xr[d]
    float4 m = make_float4(a.x + b.x, a.y + b.y, a.z + b.z, a.w + b.w);
    float4 t4 = *(const float4*)&att[l * 4];
    float lx = (m.x > 0.f) ? m.x : 0.2f * m.x;
    float ly = (m.y > 0.f) ? m.y : 0.2f * m.y;
    float lz = (m.z > 0.f) ? m.z : 0.2f * m.z;
    float lw = (m.w > 0.f) ? m.w : 0.2f * m.w;
    float partial = lx * t4.x + ly * t4.y + lz * t4.z + lw * t4.w;
    partial += __shfl_xor_sync(0xffffffffu, partial, 1);
    float ev = __expf(partial);

    if ((l & 1) == 0) {
        float* pn = &nsum[(size_t)d * 16 + (l >> 1)];
        asm volatile("red.global.add.f32 [%0], %1;" :: "l"(pn), "f"(ev) : "memory");
    }
    float* p = &xcat[(size_t)d * 512 + xofs + l * 4];
    asm volatile("red.global.add.v4.f32 [%0], {%1,%2,%3,%4};" ::
                 "l"(p), "f"(ev * a.x), "f"(ev * a.y),
                 "f"(ev * a.z), "f"(ev * a.w) : "memory");
}

// finalize: xcat[n, c*128+j] = b_c[j] + xcat / (nsum[c][n,h] + 1e-16)
__global__ void finalize_xcat(float* __restrict__ xcat, const float* __restrict__ nsum,
                              const float* __restrict__ b1, const float* __restrict__ b2,
                              const float* __restrict__ b3, const float* __restrict__ b4,
                              int N) {
    int idx = blockIdx.x * blockDim.x + threadIdx.x;   // over N*128 float4s
    if (idx >= N * 128) return;
    int n = idx >> 7, col4 = idx & 127;
    int c = col4 >> 5, j4 = col4 & 31;
    int h = j4 >> 1;
    const float* b = (c == 0) ? b1 : (c == 1) ? b2 : (c == 2) ? b3 : b4;
    float inv = 1.f / (nsum[((size_t)c * MAXN + n) * 16 + h] + 1e-16f);
    float4 v = *(float4*)&xcat[(size_t)idx * 4];
    float4 bv = *(const float4*)&b[j4 * 4];
    v.x = bv.x + v.x * inv;
    v.y = bv.y + v.y * inv;
    v.z = bv.z + v.z * inv;
    v.w = bv.w + v.w * inv;
    *(float4*)&xcat[(size_t)idx * 4] = v;
}

// ---------------- persistent edge MLP (tensor-core matvec batch) ---------------
__global__ __launch_bounds__(512, 1)
void edge_mlp(const int* __restrict__ src, const int* __restrict__ dst, int E,
              const float* __restrict__ xf,
              const float* __restrict__ lng, const float* __restrict__ lnb,
              const float* __restrict__ W, const float* __restrict__ mlpb,
              const float* __restrict__ eattr, float* __restrict__ out) {
    extern __shared__ float sm[];
    float (*Wks)[136] = (float(*)[136])sm;                 // 256*136
    float (*ps)[260]  = (float(*)[260])(sm + 256 * 136);   // 64*260
    float* lg = sm + 256 * 136 + 64 * 260;                 // 256
    float* lb = lg + 256;                                  // 256
    float* mb = lb + 256;                                  // 128

    const int tid = threadIdx.x;
    const int l = tid & 31, w = tid >> 5;
    const int g = l >> 2, tg = l & 3;
    const int wm = (w & 1) * 32;     // 2 m-warps
    const int wn = (w >> 1) * 16;    // 8 n-warps x 16 cols

#pragma unroll
    for (int i = 0; i < 16; i++) {
        int flat = tid + i * 512;
        int k = flat >> 5, n4 = flat & 31;
        float4 v = *(const float4*)&W[(size_t)k * 128 + n4 * 4];
        *(float4*)&Wks[k][n4 * 4] = tf32cvt4(v);
    }
    if (tid < 256) { lg[tid] = lng[tid]; lb[tid] = lnb[tid]; }
    if (tid < 128) mb[tid] = mlpb[tid];
    __syncthreads();

    for (int base = blockIdx.x * 64; base < E; base += gridDim.x * 64) {
#pragma unroll
        for (int e = 0; e < 4; e++) {
            int le = w * 4 + e;
            int ge = base + le;
            float4 ra, rb;
            if (ge < E) {
                int s = src[ge], d = dst[ge];
                float4 a = *(const float4*)&xf[(size_t)s * 128 + l * 4];
                float4 b = *(const float4*)&xf[(size_t)d * 128 + l * 4];
                float sum = a.x + a.y + a.z + a.w + b.x + b.y + b.z + b.w;
                float sq  = a.x * a.x + a.y * a.y + a.z * a.z + a.w * a.w
                          + b.x * b.x + b.y * b.y + b.z * b.z + b.w * b.w;
#pragma unroll
                for (int off = 16; off; off >>= 1) {
                    sum += __shfl_xor_sync(0xffffffffu, sum, off);
                    sq  += __shfl_xor_sync(0xffffffffu, sq, off);
                }
                float mu = sum * (1.f / 256.f);
                float var = sq * (1.f / 256.f) - mu * mu;
                float rs = rsqrtf(var + 1e-5f);
                float4 ga = *(const float4*)&lg[l * 4];
                float4 ba = *(const float4*)&lb[l * 4];
                float4 gb = *(const float4*)&lg[128 + l * 4];
                float4 bb = *(const float4*)&lb[128 + l * 4];
                ra.x = fmaxf(0.f, (a.x - mu) * rs * ga.x + ba.x);
                ra.y = fmaxf(0.f, (a.y - mu) * rs * ga.y + ba.y);
                ra.z = fmaxf(0.f, (a.z - mu) * rs * ga.z + ba.z);
                ra.w = fmaxf(0.f, (a.w - mu) * rs * ga.w + ba.w);
                rb.x = fmaxf(0.f, (b.x - mu) * rs * gb.x + bb.x);
                rb.y = fmaxf(0.f, (b.y - mu) * rs * gb.y + bb.y);
                rb.z = fmaxf(0.f, (b.z - mu) * rs * gb.z + bb.z);
                rb.w = fmaxf(0.f, (b.w - mu) * rs * gb.w + bb.w);
            } else {
                ra = rb = make_float4(0.f, 0.f, 0.f, 0.f);
            }
            *(float4*)&ps[le][l * 4]       = tf32cvt4(ra);
            *(float4*)&ps[le][128 + l * 4] = tf32cvt4(rb);
        }
        __syncthreads();

        float c[2][2][4];
#pragma unroll
        for (int mt = 0; mt < 2; mt++)
#pragma unroll
            for (int nt = 0; nt < 2; nt++)
#pragma unroll
                for (int i = 0; i < 4; i++) c[mt][nt][i] = 0.f;

#pragma unroll 4
        for (int k8 = 0; k8 < 32; k8++) {
            const int kb = k8 * 8;
            uint32_t a[2][4], b[2][2];
#pragma unroll
            for (int mt = 0; mt < 2; mt++) {
                int m = wm + mt * 16;
                a[mt][0] = __float_as_uint(ps[m + g][kb + tg]);
                a[mt][1] = __float_as_uint(ps[m + 8 + g][kb + tg]);
                a[mt][2] = __float_as_uint(ps[m + g][kb + tg + 4]);
                a[mt][3] = __float_as_uint(ps[m + 8 + g][kb + tg + 4]);
            }
#pragma unroll
            for (int nt = 0; nt < 2; nt++) {
                int n = wn + nt * 8;
                b[nt][0] = __float_as_uint(Wks[kb + tg][n + g]);
                b[nt][1] = __float_as_uint(Wks[kb + tg + 4][n + g]);
            }
#pragma unroll
            for (int mt = 0; mt < 2; mt++)
#pragma unroll
                for (int nt = 0; nt < 2; nt++)
                    mma_tf32(c[mt][nt], a[mt], b[nt]);
        }

#pragma unroll
        for (int mt = 0; mt < 2; mt++) {
#pragma unroll
            for (int nt = 0; nt < 2; nt++) {
                int le = wm + mt * 16 + g;
                int col = wn + nt * 8 + tg * 2;
                float2 bv = *(const float2*)&mb[col];
                int ge0 = base + le;
                int ge1 = ge0 + 8;
                if (ge0 < E) {
                    float2 ea = *(const float2*)&eattr[(size_t)ge0 * 128 + col];
                    float2 o = make_float2(c[mt][nt][0] + bv.x + ea.x,
                                           c[mt][nt][1] + bv.y + ea.y);
                    *(float2*)&out[(size_t)ge0 * 128 + col] = o;
                }
                if (ge1 < E) {
                    float2 ea = *(const float2*)&eattr[(size_t)ge1 * 128 + col];
                    float2 o = make_float2(c[mt][nt][2] + bv.x + ea.x,
                                           c[mt][nt][3] + bv.y + ea.y);
                    *(float2*)&out[(size_t)ge1 * 128 + col] = o;
                }
            }
        }
        __syncthreads();   // ps reused next batch
    }
}

// dual_out[i] = (idx==E) ? ones : edge_attr_new[idx]
__global__ void dual_gather(const int* __restrict__ idx, int M, int E,
                            const float* __restrict__ ea, float* __restrict__ out) {
    int tid = blockIdx.x * blockDim.x + threadIdx.x;
    if (tid >= M * 32) return;
    int i = tid >> 5, l = tid & 31;
    int id = idx[i];
    float4 v;
    if (id >= E) v = make_float4(1.f, 1.f, 1.f, 1.f);
    else         v = *(const float4*)&ea[(size_t)id * 128 + l * 4];
    *(float4*)&out[(size_t)i * 128 + l * 4] = v;
}

// ---------------- host orchestration ------------------------------------------

static const int MLP_SMEM = (256 * 136 + 64 * 260 + 256 + 256 + 128) * 4;  // ~204 KB

extern "C" void kernel_launch(void* const* d_in, const int* in_sizes, int n_in,
                              void* d_out, int out_size) {
    const float* x         = (const float*)d_in[0];
    const int*   ei[4]     = {(const int*)d_in[1], (const int*)d_in[2],
                              (const int*)d_in[3], (const int*)d_in[4]};
    const float* dual_attr = (const float*)d_in[5];
    const float* edge_attr = (const float*)d_in[6];
    const int*   oemap     = (const int*)d_in[7];

    const float *Wl[4], *Wr[4], *att[4], *bb[4];
    int p = 8;
    for (int c = 0; c < 4; c++) {
        Wl[c]  = (const float*)d_in[p++];
        Wr[c]  = (const float*)d_in[p++];
        att[c] = (const float*)d_in[p++];
        bb[c]  = (const float*)d_in[p++];
    }
    const float* We1    = (const float*)d_in[24];
    const float* fuse_W = (const float*)d_in[25];
    const float* fuse_b = (const float*)d_in[26];
    const float* ln_g   = (const float*)d_in[27];
    const float* ln_b   = (const float*)d_in[28];
    const float* mlp_W  = (const float*)d_in[29];
    const float* mlp_b  = (const float*)d_in[30];

    const int N     = in_sizes[0] / 128;
    const int Ec[4] = {in_sizes[1] / 2, in_sizes[2] / 2, in_sizes[3] / 2, in_sizes[4] / 2};
    const int M_oe  = in_sizes[7];
    const int E1    = Ec[0];

    float *xlr, *wcat, *xcat, *nsum;
    cudaGetSymbolAddress((void**)&xlr,  g_xlr);
    cudaGetSymbolAddress((void**)&wcat, g_wcat);
    cudaGetSymbolAddress((void**)&xcat, g_xcat);
    cudaGetSymbolAddress((void**)&nsum, g_nsum);

    cudaFuncSetAttribute(edge_mlp, cudaFuncAttributeMaxDynamicSharedMemorySize, MLP_SMEM);

    // zero accumulators (graph-capturable async memsets)
    cudaMemsetAsync(xcat, 0, (size_t)N * 512 * sizeof(float), 0);
    cudaMemsetAsync(nsum, 0, (size_t)4 * MAXN * 16 * sizeof(float), 0);

    // pack (Wl|Wr) x 4 -> wcat [128,1024]
    pack_w<<<(128 * 1024 + 255) / 256, 256>>>(Wl[0], Wr[0], Wl[1], Wr[1],
                                              Wl[2], Wr[2], Wl[3], Wr[3], wcat);

    // one wide GEMM for all 8 node projections: xlr = x @ wcat
    {
        dim3 grid((N + 127) / 128, 8);
        gemm_mma<128, 1024, 1024><<<grid, 256>>>(x, wcat, nullptr, xlr, N);
    }

    // conv0: fused (dual_attr @ We1) + edge softmax scatter (pre never hits DRAM)
    edge_conv0<<<(E1 + 127) / 128, 256>>>(dual_attr, We1, ei[0], ei[0] + E1, E1,
                                          xlr, att[0], nsum, xcat);

    // convs 1..3: single fused edge pass each
    for (int c = 1; c < 4; c++) {
        const int E = Ec[c];
        edge_fused<<<(E + 7) / 8, 256>>>(ei[c], ei[c] + E, E, xlr, c * 256,
                                         att[c], nsum + (size_t)c * MAXN * 16,
                                         xcat, c * 128);
    }

    // normalize + bias
    finalize_xcat<<<(N * 128 + 255) / 256, 256>>>(xcat, nsum,
                                                  bb[0], bb[1], bb[2], bb[3], N);

    // fuse: xf = xcat @ fuse_W + fuse_b  -> output section 0
    float* xf = (float*)d_out;
    {
        dim3 grid((N + 127) / 128, 1);
        gemm_mma<512, 128, 128><<<grid, 256>>>(xcat, fuse_W, fuse_b, xf, N);
    }

    // edge MLP -> output section 1 (persistent, tensor-core batch matvec)
    float* eout = (float*)d_out + (size_t)N * 128;
    edge_mlp<<<148, 512, MLP_SMEM>>>(ei[0], ei[0] + E1, E1, xf, ln_g, ln_b,
                                     mlp_W, mlp_b, edge_attr, eout);

    // dual gather -> output section 2
    float* dout = eout + (size_t)E1 * 128;
    dual_gather<<<(M_oe * 32 + 255) / 256, 256>>>(oemap, M_oe, E1, eout, dout);
}

// round 16
// speedup vs baseline: 21.3899x; 1.0048x over previous
#include <cuda_runtime.h>
#include <cstdint>

// ---------------- scratch (device globals; no allocation allowed) -------------
#define MAXN 50000
#define MAXE 500000

__device__ float g_xlr[(size_t)MAXN * 1024];  // [N][8*128]: (Wl|Wr) x 4 convs
__device__ float g_wcat[128 * 1024];          // packed weights [k][1024]
__device__ float g_bcat[512];                 // packed conv biases
__device__ float g_xcat[MAXN * 512];
__device__ float g_nsum[4 * MAXN * 16];       // per-conv segment sums

// ---------------- helpers -----------------------------------------------------

__device__ __forceinline__ uint32_t tf32u(float x) {
    uint32_t u; asm("cvt.rna.tf32.f32 %0, %1;" : "=r"(u) : "f"(x)); return u;
}
__device__ __forceinline__ float4 tf32cvt4(float4 v) {
    float4 r;
    r.x = __uint_as_float(tf32u(v.x));
    r.y = __uint_as_float(tf32u(v.y));
    r.z = __uint_as_float(tf32u(v.z));
    r.w = __uint_as_float(tf32u(v.w));
    return r;
}
__device__ __forceinline__ void mma_tf32(float* c, const uint32_t* a, const uint32_t* b) {
    asm volatile(
        "mma.sync.aligned.m16n8k8.row.col.f32.tf32.tf32.f32 "
        "{%0,%1,%2,%3}, {%4,%5,%6,%7}, {%8,%9}, {%0,%1,%2,%3};\n"
        : "+f"(c[0]), "+f"(c[1]), "+f"(c[2]), "+f"(c[3])
        : "r"(a[0]), "r"(a[1]), "r"(a[2]), "r"(a[3]), "r"(b[0]), "r"(b[1]));
}

// pack 8 [128,128] weight mats into wcat[k][w*128+j]; biases into bcat
__global__ void pack_w(const float* __restrict__ w0, const float* __restrict__ w1,
                       const float* __restrict__ w2, const float* __restrict__ w3,
                       const float* __restrict__ w4, const float* __restrict__ w5,
                       const float* __restrict__ w6, const float* __restrict__ w7,
                       float* __restrict__ wcat,
                       const float* __restrict__ b0, const float* __restrict__ b1,
                       const float* __restrict__ b2, const float* __restrict__ b3,
                       float* __restrict__ bcat) {
    int idx = blockIdx.x * blockDim.x + threadIdx.x;
    if (idx < 512) {
        const float* bs[4] = {b0, b1, b2, b3};
        bcat[idx] = bs[idx >> 7][idx & 127];
    }
    if (idx >= 128 * 1024) return;
    int w = (idx >> 14), rem = idx & 16383;
    int k = rem >> 7, j = rem & 127;
    const float* ws[8] = {w0, w1, w2, w3, w4, w5, w6, w7};
    wcat[k * 1024 + w * 128 + j] = ws[w][k * 128 + j];
}

// ---------------- tf32 tensor-core GEMM: out[M,NW] = A[M,K] @ W[K,NW] (+bias)
template <int K, int NW, int OSTRIDE>
__global__ __launch_bounds__(256)
void gemm_mma(const float* __restrict__ A, const float* __restrict__ W,
              const float* __restrict__ bias, float* __restrict__ out, int M) {
    __shared__ float As[128][36];   // [m][k]
    __shared__ float Ws[32][136];   // [k][n]

    const int tid = threadIdx.x;
    const int l = tid & 31, w = tid >> 5;
    const int g = l >> 2, tg = l & 3;
    const int wm = (w & 3) * 32;
    const int wn = (w >> 2) * 64;
    const int r0 = blockIdx.x * 128;
    const int c0 = blockIdx.y * 128;

    float c[2][8][4];
#pragma unroll
    for (int mt = 0; mt < 2; mt++)
#pragma unroll
        for (int nt = 0; nt < 8; nt++)
#pragma unroll
            for (int i = 0; i < 4; i++) c[mt][nt][i] = 0.f;

    for (int kt = 0; kt < K; kt += 32) {
#pragma unroll
        for (int i = 0; i < 4; i++) {
            int flat = tid + i * 256;
            int r = flat >> 3, kq = flat & 7;
            float4 v = (r0 + r < M)
                ? *(const float4*)&A[(size_t)(r0 + r) * K + kt + kq * 4]
                : make_float4(0.f, 0.f, 0.f, 0.f);
            *(float4*)&As[r][kq * 4] = tf32cvt4(v);
        }
#pragma unroll
        for (int i = 0; i < 4; i++) {
            int flat = tid + i * 256;
            int k = flat >> 5, n4 = flat & 31;
            float4 v = *(const float4*)&W[(size_t)(kt + k) * NW + c0 + n4 * 4];
            *(float4*)&Ws[k][n4 * 4] = tf32cvt4(v);
        }
        __syncthreads();

#pragma unroll
        for (int k8 = 0; k8 < 4; k8++) {
            const int kb = k8 * 8;
            uint32_t a[2][4], b[8][2];
#pragma unroll
            for (int mt = 0; mt < 2; mt++) {
                int m = wm + mt * 16;
                a[mt][0] = __float_as_uint(As[m + g][kb + tg]);
                a[mt][1] = __float_as_uint(As[m + 8 + g][kb + tg]);
                a[mt][2] = __float_as_uint(As[m + g][kb + tg + 4]);
                a[mt][3] = __float_as_uint(As[m + 8 + g][kb + tg + 4]);
            }
#pragma unroll
            for (int nt = 0; nt < 8; nt++) {
                int n = wn + nt * 8;
                b[nt][0] = __float_as_uint(Ws[kb + tg][n + g]);
                b[nt][1] = __float_as_uint(Ws[kb + tg + 4][n + g]);
            }
#pragma unroll
            for (int mt = 0; mt < 2; mt++)
#pragma unroll
                for (int nt = 0; nt < 8; nt++)
                    mma_tf32(c[mt][nt], a[mt], b[nt]);
        }
        __syncthreads();
    }

#pragma unroll
    for (int mt = 0; mt < 2; mt++) {
#pragma unroll
        for (int nt = 0; nt < 8; nt++) {
            int row = r0 + wm + mt * 16 + g;
            int col = c0 + wn + nt * 8 + tg * 2;
            float2 bv = bias ? *(const float2*)&bias[col] : make_float2(0.f, 0.f);
            if (row < M) {
                float2 o = make_float2(c[mt][nt][0] + bv.x, c[mt][nt][1] + bv.y);
                *(float2*)&out[(size_t)row * OSTRIDE + col] = o;
            }
            if (row + 8 < M) {
                float2 o = make_float2(c[mt][nt][2] + bv.x, c[mt][nt][3] + bv.y);
                *(float2*)&out[(size_t)(row + 8) * OSTRIDE + col] = o;
            }
        }
    }
}

// ---------------- fuse GEMM with inline xcat normalization ---------------------
// xf[M,128] = (xcat_raw/nsum + bcat) @ fuse_W + fuse_b. The normalize+bias of
// the former finalize_xcat pass happens in the A-staging loads (fp32, same
// order as before), deleting a full 200MB pass over xcat.
__global__ __launch_bounds__(256)
void gemm_fuse(const float* __restrict__ A, const float* __restrict__ nsum,
               const float* __restrict__ bcat,
               const float* __restrict__ W, const float* __restrict__ bias,
               float* __restrict__ out, int M) {
    __shared__ float As[128][36];
    __shared__ float Ws[32][136];

    const int tid = threadIdx.x;
    const int l = tid & 31, w = tid >> 5;
    const int g = l >> 2, tg = l & 3;
    const int wm = (w & 3) * 32;
    const int wn = (w >> 2) * 64;
    const int r0 = blockIdx.x * 128;

    float c[2][8][4];
#pragma unroll
    for (int mt = 0; mt < 2; mt++)
#pragma unroll
        for (int nt = 0; nt < 8; nt++)
#pragma unroll
            for (int i = 0; i < 4; i++) c[mt][nt][i] = 0.f;

    for (int kt = 0; kt < 512; kt += 32) {
#pragma unroll
        for (int i = 0; i < 4; i++) {
            int flat = tid + i * 256;
            int r = flat >> 3, kq = flat & 7;
            int row = r0 + r;
            int col = kt + kq * 4;
            float4 v = make_float4(0.f, 0.f, 0.f, 0.f);
            if (row < M) {
                v = *(const float4*)&A[(size_t)row * 512 + col];
                int cv = col >> 7, j = col & 127, h = j >> 3;
                float inv = 1.f / (nsum[((size_t)cv * MAXN + row) * 16 + h] + 1e-16f);
                float4 bv = *(const float4*)&bcat[col];
                v.x = bv.x + v.x * inv;
                v.y = bv.y + v.y * inv;
                v.z = bv.z + v.z * inv;
                v.w = bv.w + v.w * inv;
            }
            *(float4*)&As[r][kq * 4] = tf32cvt4(v);
        }
#pragma unroll
        for (int i = 0; i < 4; i++) {
            int flat = tid + i * 256;
            int k = flat >> 5, n4 = flat & 31;
            float4 v = *(const float4*)&W[(size_t)(kt + k) * 128 + n4 * 4];
            *(float4*)&Ws[k][n4 * 4] = tf32cvt4(v);
        }
        __syncthreads();

#pragma unroll
        for (int k8 = 0; k8 < 4; k8++) {
            const int kb = k8 * 8;
            uint32_t a[2][4], b[8][2];
#pragma unroll
            for (int mt = 0; mt < 2; mt++) {
                int m = wm + mt * 16;
                a[mt][0] = __float_as_uint(As[m + g][kb + tg]);
                a[mt][1] = __float_as_uint(As[m + 8 + g][kb + tg]);
                a[mt][2] = __float_as_uint(As[m + g][kb + tg + 4]);
                a[mt][3] = __float_as_uint(As[m + 8 + g][kb + tg + 4]);
            }
#pragma unroll
            for (int nt = 0; nt < 8; nt++) {
                int n = wn + nt * 8;
                b[nt][0] = __float_as_uint(Ws[kb + tg][n + g]);
                b[nt][1] = __float_as_uint(Ws[kb + tg + 4][n + g]);
            }
#pragma unroll
            for (int mt = 0; mt < 2; mt++)
#pragma unroll
                for (int nt = 0; nt < 8; nt++)
                    mma_tf32(c[mt][nt], a[mt], b[nt]);
        }
        __syncthreads();
    }

#pragma unroll
    for (int mt = 0; mt < 2; mt++) {
#pragma unroll
        for (int nt = 0; nt < 8; nt++) {
            int row = r0 + wm + mt * 16 + g;
            int col = wn + nt * 8 + tg * 2;
            float2 bv = *(const float2*)&bias[col];
            if (row < M) {
                float2 o = make_float2(c[mt][nt][0] + bv.x, c[mt][nt][1] + bv.y);
                *(float2*)&out[(size_t)row * 128 + col] = o;
            }
            if (row + 8 < M) {
                float2 o = make_float2(c[mt][nt][2] + bv.x, c[mt][nt][3] + bv.y);
                *(float2*)&out[(size_t)(row + 8) * 128 + col] = o;
            }
        }
    }
}

// ---------------- conv0: fused (dual_attr @ We1) GEMM + edge softmax pass ------
__global__ __launch_bounds__(256)
void edge_conv0(const float* __restrict__ A /*dual_attr*/, const float* __restrict__ W /*We1*/,
                const int* __restrict__ src, const int* __restrict__ dst, int E,
                const float* __restrict__ xlr, const float* __restrict__ att,
                float* __restrict__ nsum, float* __restrict__ xcat) {
    __shared__ float smu[128 * 136];            // union: phase1 As+Ws | phase3 pre_s
    float (*As)[36]   = (float(*)[36])smu;
    float (*Ws)[136]  = (float(*)[136])(smu + 128 * 36);
    float (*pre_s)[136] = (float(*)[136])smu;

    const int tid = threadIdx.x;
    const int l = tid & 31, w = tid >> 5;
    const int g = l >> 2, tg = l & 3;
    const int wm = (w & 3) * 32;
    const int wn = (w >> 2) * 64;
    const int r0 = blockIdx.x * 128;            // first edge of tile

    float c[2][8][4];
#pragma unroll
    for (int mt = 0; mt < 2; mt++)
#pragma unroll
        for (int nt = 0; nt < 8; nt++)
#pragma unroll
            for (int i = 0; i < 4; i++) c[mt][nt][i] = 0.f;

    for (int kt = 0; kt < 128; kt += 32) {
#pragma unroll
        for (int i = 0; i < 4; i++) {
            int flat = tid + i * 256;
            int r = flat >> 3, kq = flat & 7;
            float4 v = (r0 + r < E)
                ? *(const float4*)&A[(size_t)(r0 + r) * 128 + kt + kq * 4]
                : make_float4(0.f, 0.f, 0.f, 0.f);
            *(float4*)&As[r][kq * 4] = tf32cvt4(v);
        }
#pragma unroll
        for (int i = 0; i < 4; i++) {
            int flat = tid + i * 256;
            int k = flat >> 5, n4 = flat & 31;
            float4 v = *(const float4*)&W[(size_t)(kt + k) * 128 + n4 * 4];
            *(float4*)&Ws[k][n4 * 4] = tf32cvt4(v);
        }
        __syncthreads();

#pragma unroll
        for (int k8 = 0; k8 < 4; k8++) {
            const int kb = k8 * 8;
            uint32_t a[2][4], b[8][2];
#pragma unroll
            for (int mt = 0; mt < 2; mt++) {
                int m = wm + mt * 16;
                a[mt][0] = __float_as_uint(As[m + g][kb + tg]);
                a[mt][1] = __float_as_uint(As[m + 8 + g][kb + tg]);
                a[mt][2] = __float_as_uint(As[m + g][kb + tg + 4]);
                a[mt][3] = __float_as_uint(As[m + 8 + g][kb + tg + 4]);
            }
#pragma unroll
            for (int nt = 0; nt < 8; nt++) {
                int n = wn + nt * 8;
                b[nt][0] = __float_as_uint(Ws[kb + tg][n + g]);
                b[nt][1] = __float_as_uint(Ws[kb + tg + 4][n + g]);
            }
#pragma unroll
            for (int mt = 0; mt < 2; mt++)
#pragma unroll
                for (int nt = 0; nt < 8; nt++)
                    mma_tf32(c[mt][nt], a[mt], b[nt]);
        }
        __syncthreads();
    }

    // fragments -> pre_s (As/Ws dead)
#pragma unroll
    for (int mt = 0; mt < 2; mt++) {
#pragma unroll
        for (int nt = 0; nt < 8; nt++) {
            int lr = wm + mt * 16 + g;
            int col = wn + nt * 8 + tg * 2;
            *(float2*)&pre_s[lr][col]     = make_float2(c[mt][nt][0], c[mt][nt][1]);
            *(float2*)&pre_s[lr + 8][col] = make_float2(c[mt][nt][2], c[mt][nt][3]);
        }
    }
    __syncthreads();

    // each warp handles 16 edges
#pragma unroll 4
    for (int i = 0; i < 16; i++) {
        int le = w * 16 + i;
        int e = r0 + le;
        if (e >= E) break;
        int s = src[e], d = dst[e];
        float4 a = *(const float4*)&xlr[(size_t)s * 1024 + l * 4];
        float4 b = *(const float4*)&xlr[(size_t)d * 1024 + 128 + l * 4];
        float4 p = *(const float4*)&pre_s[le][l * 4];
        float4 m = make_float4(a.x + b.x + p.x, a.y + b.y + p.y,
                               a.z + b.z + p.z, a.w + b.w + p.w);
        float4 t4 = *(const float4*)&att[l * 4];
        float lx = (m.x > 0.f) ? m.x : 0.2f * m.x;
        float ly = (m.y > 0.f) ? m.y : 0.2f * m.y;
        float lz = (m.z > 0.f) ? m.z : 0.2f * m.z;
        float lw = (m.w > 0.f) ? m.w : 0.2f * m.w;
        float partial = lx * t4.x + ly * t4.y + lz * t4.z + lw * t4.w;
        partial += __shfl_xor_sync(0xffffffffu, partial, 1);
        float ev = __expf(partial);

        if ((l & 1) == 0) {
            float* pn = &nsum[(size_t)d * 16 + (l >> 1)];
            asm volatile("red.global.add.f32 [%0], %1;" :: "l"(pn), "f"(ev) : "memory");
        }
        float* pp = &xcat[(size_t)d * 512 + l * 4];
        asm volatile("red.global.add.v4.f32 [%0], {%1,%2,%3,%4};" ::
                     "l"(pp), "f"(ev * a.x), "f"(ev * a.y),
                     "f"(ev * a.z), "f"(ev * a.w) : "memory");
    }
}

// ---------------- fused edge pass for convs 1-3 in ONE launch -------------------
struct EdgeAll {
    const int* src[3];
    const int* dst[3];
    const float* att[3];
    float* nsum[3];
    int E[3];
    int cofs[3];
    int xofs[3];
    int nb[3];      // blocks per conv
};

__global__ void edge_fused_all(EdgeAll P, const float* __restrict__ xlr,
                               float* __restrict__ xcat) {
    int b = blockIdx.x;
    int c = 0;
    if (b >= P.nb[0]) { b -= P.nb[0]; c = 1; }
    if (c == 1 && b >= P.nb[1]) { b -= P.nb[1]; c = 2; }

    const int l = threadIdx.x & 31;
    const int slot = threadIdx.x >> 5;
    const int e = b * 8 + slot;
    if (e >= P.E[c]) return;
    int s = P.src[c][e], d = P.dst[c][e];
    const int cofs = P.cofs[c];
    float4 a = *(const float4*)&xlr[(size_t)s * 1024 + cofs + l * 4];
    float4 bb = *(const float4*)&xlr[(size_t)d * 1024 + cofs + 128 + l * 4];
    float4 m = make_float4(a.x + bb.x, a.y + bb.y, a.z + bb.z, a.w + bb.w);
    float4 t4 = *(const float4*)&P.att[c][l * 4];
    float lx = (m.x > 0.f) ? m.x : 0.2f * m.x;
    float ly = (m.y > 0.f) ? m.y : 0.2f * m.y;
    float lz = (m.z > 0.f) ? m.z : 0.2f * m.z;
    float lw = (m.w > 0.f) ? m.w : 0.2f * m.w;
    float partial = lx * t4.x + ly * t4.y + lz * t4.z + lw * t4.w;
    partial += __shfl_xor_sync(0xffffffffu, partial, 1);
    float ev = __expf(partial);

    if ((l & 1) == 0) {
        float* pn = &P.nsum[c][(size_t)d * 16 + (l >> 1)];
        asm volatile("red.global.add.f32 [%0], %1;" :: "l"(pn), "f"(ev) : "memory");
    }
    float* p = &xcat[(size_t)d * 512 + P.xofs[c] + l * 4];
    asm volatile("red.global.add.v4.f32 [%0], {%1,%2,%3,%4};" ::
                 "l"(p), "f"(ev * a.x), "f"(ev * a.y),
                 "f"(ev * a.z), "f"(ev * a.w) : "memory");
}

// ---------------- persistent edge MLP (tensor-core matvec batch) ---------------
__global__ __launch_bounds__(512, 1)
void edge_mlp(const int* __restrict__ src, const int* __restrict__ dst, int E,
              const float* __restrict__ xf,
              const float* __restrict__ lng, const float* __restrict__ lnb,
              const float* __restrict__ W, const float* __restrict__ mlpb,
              const float* __restrict__ eattr, float* __restrict__ out) {
    extern __shared__ float sm[];
    float (*Wks)[136] = (float(*)[136])sm;                 // 256*136
    float (*ps)[260]  = (float(*)[260])(sm + 256 * 136);   // 64*260
    float* lg = sm + 256 * 136 + 64 * 260;                 // 256
    float* lb = lg + 256;                                  // 256
    float* mb = lb + 256;                                  // 128

    const int tid = threadIdx.x;
    const int l = tid & 31, w = tid >> 5;
    const int g = l >> 2, tg = l & 3;
    const int wm = (w & 1) * 32;     // 2 m-warps
    const int wn = (w >> 1) * 16;    // 8 n-warps x 16 cols

#pragma unroll
    for (int i = 0; i < 16; i++) {
        int flat = tid + i * 512;
        int k = flat >> 5, n4 = flat & 31;
        float4 v = *(const float4*)&W[(size_t)k * 128 + n4 * 4];
        *(float4*)&Wks[k][n4 * 4] = tf32cvt4(v);
    }
    if (tid < 256) { lg[tid] = lng[tid]; lb[tid] = lnb[tid]; }
    if (tid < 128) mb[tid] = mlpb[tid];
    __syncthreads();

    for (int base = blockIdx.x * 64; base < E; base += gridDim.x * 64) {
        // ---- LN phase: batch all gathers first (8 LDG.128 in flight) ----
        int ss[4], dd[4];
#pragma unroll
        for (int e = 0; e < 4; e++) {
            int ge = base + w * 4 + e;
            ss[e] = (ge < E) ? src[ge] : 0;
            dd[e] = (ge < E) ? dst[ge] : 0;
        }
        float4 A4[4], B4[4];
#pragma unroll
        for (int e = 0; e < 4; e++) {
            A4[e] = *(const float4*)&xf[(size_t)ss[e] * 128 + l * 4];
            B4[e] = *(const float4*)&xf[(size_t)dd[e] * 128 + l * 4];
        }
#pragma unroll
        for (int e = 0; e < 4; e++) {
            int le = w * 4 + e;
            int ge = base + le;
            float4 a = A4[e], b = B4[e];
            float4 ra, rb;
            if (ge < E) {
                float sum = a.x + a.y + a.z + a.w + b.x + b.y + b.z + b.w;
                float sq  = a.x * a.x + a.y * a.y + a.z * a.z + a.w * a.w
                          + b.x * b.x + b.y * b.y + b.z * b.z + b.w * b.w;
#pragma unroll
                for (int off = 16; off; off >>= 1) {
                    sum += __shfl_xor_sync(0xffffffffu, sum, off);
                    sq  += __shfl_xor_sync(0xffffffffu, sq, off);
                }
                float mu = sum * (1.f / 256.f);
                float var = sq * (1.f / 256.f) - mu * mu;
                float rs = rsqrtf(var + 1e-5f);
                float4 ga = *(const float4*)&lg[l * 4];
                float4 ba = *(const float4*)&lb[l * 4];
                float4 gb = *(const float4*)&lg[128 + l * 4];
                float4 bb = *(const float4*)&lb[128 + l * 4];
                ra.x = fmaxf(0.f, (a.x - mu) * rs * ga.x + ba.x);
                ra.y = fmaxf(0.f, (a.y - mu) * rs * ga.y + ba.y);
                ra.z = fmaxf(0.f, (a.z - mu) * rs * ga.z + ba.z);
                ra.w = fmaxf(0.f, (a.w - mu) * rs * ga.w + ba.w);
                rb.x = fmaxf(0.f, (b.x - mu) * rs * gb.x + bb.x);
                rb.y = fmaxf(0.f, (b.y - mu) * rs * gb.y + bb.y);
                rb.z = fmaxf(0.f, (b.z - mu) * rs * gb.z + bb.z);
                rb.w = fmaxf(0.f, (b.w - mu) * rs * gb.w + bb.w);
            } else {
                ra = rb = make_float4(0.f, 0.f, 0.f, 0.f);
            }
            *(float4*)&ps[le][l * 4]       = tf32cvt4(ra);
            *(float4*)&ps[le][128 + l * 4] = tf32cvt4(rb);
        }
        __syncthreads();

        float c[2][2][4];
#pragma unroll
        for (int mt = 0; mt < 2; mt++)
#pragma unroll
            for (int nt = 0; nt < 2; nt++)
#pragma unroll
                for (int i = 0; i < 4; i++) c[mt][nt][i] = 0.f;

#pragma unroll 4
        for (int k8 = 0; k8 < 32; k8++) {
            const int kb = k8 * 8;
            uint32_t a[2][4], b[2][2];
#pragma unroll
            for (int mt = 0; mt < 2; mt++) {
                int m = wm + mt * 16;
                a[mt][0] = __float_as_uint(ps[m + g][kb + tg]);
                a[mt][1] = __float_as_uint(ps[m + 8 + g][kb + tg]);
                a[mt][2] = __float_as_uint(ps[m + g][kb + tg + 4]);
                a[mt][3] = __float_as_uint(ps[m + 8 + g][kb + tg + 4]);
            }
#pragma unroll
            for (int nt = 0; nt < 2; nt++) {
                int n = wn + nt * 8;
                b[nt][0] = __float_as_uint(Wks[kb + tg][n + g]);
                b[nt][1] = __float_as_uint(Wks[kb + tg + 4][n + g]);
            }
#pragma unroll
            for (int mt = 0; mt < 2; mt++)
#pragma unroll
                for (int nt = 0; nt < 2; nt++)
                    mma_tf32(c[mt][nt], a[mt], b[nt]);
        }

#pragma unroll
        for (int mt = 0; mt < 2; mt++) {
#pragma unroll
            for (int nt = 0; nt < 2; nt++) {
                int le = wm + mt * 16 + g;
                int col = wn + nt * 8 + tg * 2;
                float2 bv = *(const float2*)&mb[col];
                int ge0 = base + le;
                int ge1 = ge0 + 8;
                if (ge0 < E) {
                    float2 ea = *(const float2*)&eattr[(size_t)ge0 * 128 + col];
                    float2 o = make_float2(c[mt][nt][0] + bv.x + ea.x,
                                           c[mt][nt][1] + bv.y + ea.y);
                    *(float2*)&out[(size_t)ge0 * 128 + col] = o;
                }
                if (ge1 < E) {
                    float2 ea = *(const float2*)&eattr[(size_t)ge1 * 128 + col];
                    float2 o = make_float2(c[mt][nt][2] + bv.x + ea.x,
                                           c[mt][nt][3] + bv.y + ea.y);
                    *(float2*)&out[(size_t)ge1 * 128 + col] = o;
                }
            }
        }
        __syncthreads();   // ps reused next batch
    }
}

// dual_out[i] = (idx==E) ? ones : edge_attr_new[idx]
__global__ void dual_gather(const int* __restrict__ idx, int M, int E,
                            const float* __restrict__ ea, float* __restrict__ out) {
    int tid = blockIdx.x * blockDim.x + threadIdx.x;
    if (tid >= M * 32) return;
    int i = tid >> 5, l = tid & 31;
    int id = idx[i];
    float4 v;
    if (id >= E) v = make_float4(1.f, 1.f, 1.f, 1.f);
    else         v = *(const float4*)&ea[(size_t)id * 128 + l * 4];
    *(float4*)&out[(size_t)i * 128 + l * 4] = v;
}

// ---------------- host orchestration ------------------------------------------

static const int MLP_SMEM = (256 * 136 + 64 * 260 + 256 + 256 + 128) * 4;  // ~204 KB

extern "C" void kernel_launch(void* const* d_in, const int* in_sizes, int n_in,
                              void* d_out, int out_size) {
    const float* x         = (const float*)d_in[0];
    const int*   ei[4]     = {(const int*)d_in[1], (const int*)d_in[2],
                              (const int*)d_in[3], (const int*)d_in[4]};
    const float* dual_attr = (const float*)d_in[5];
    const float* edge_attr = (const float*)d_in[6];
    const int*   oemap     = (const int*)d_in[7];

    const float *Wl[4], *Wr[4], *att[4], *bb[4];
    int p = 8;
    for (int c = 0; c < 4; c++) {
        Wl[c]  = (const float*)d_in[p++];
        Wr[c]  = (const float*)d_in[p++];
        att[c] = (const float*)d_in[p++];
        bb[c]  = (const float*)d_in[p++];
    }
    const float* We1    = (const float*)d_in[24];
    const float* fuse_W = (const float*)d_in[25];
    const float* fuse_b = (const float*)d_in[26];
    const float* ln_g   = (const float*)d_in[27];
    const float* ln_b   = (const float*)d_in[28];
    const float* mlp_W  = (const float*)d_in[29];
    const float* mlp_b  = (const float*)d_in[30];

    const int N     = in_sizes[0] / 128;
    const int Ec[4] = {in_sizes[1] / 2, in_sizes[2] / 2, in_sizes[3] / 2, in_sizes[4] / 2};
    const int M_oe  = in_sizes[7];
    const int E1    = Ec[0];

    float *xlr, *wcat, *bcat, *xcat, *nsum;
    cudaGetSymbolAddress((void**)&xlr,  g_xlr);
    cudaGetSymbolAddress((void**)&wcat, g_wcat);
    cudaGetSymbolAddress((void**)&bcat, g_bcat);
    cudaGetSymbolAddress((void**)&xcat, g_xcat);
    cudaGetSymbolAddress((void**)&nsum, g_nsum);

    cudaFuncSetAttribute(edge_mlp, cudaFuncAttributeMaxDynamicSharedMemorySize, MLP_SMEM);

    // zero accumulators (graph-capturable async memsets)
    cudaMemsetAsync(xcat, 0, (size_t)N * 512 * sizeof(float), 0);
    cudaMemsetAsync(nsum, 0, (size_t)4 * MAXN * 16 * sizeof(float), 0);

    // pack (Wl|Wr) x 4 -> wcat [128,1024]; biases -> bcat[512]
    pack_w<<<(128 * 1024 + 255) / 256, 256>>>(Wl[0], Wr[0], Wl[1], Wr[1],
                                              Wl[2], Wr[2], Wl[3], Wr[3], wcat,
                                              bb[0], bb[1], bb[2], bb[3], bcat);

    // one wide GEMM for all 8 node projections: xlr = x @ wcat
    {
        dim3 grid((N + 127) / 128, 8);
        gemm_mma<128, 1024, 1024><<<grid, 256>>>(x, wcat, nullptr, xlr, N);
    }

    // conv0: fused (dual_attr @ We1) + edge softmax scatter (pre never hits DRAM)
    edge_conv0<<<(E1 + 127) / 128, 256>>>(dual_attr, We1, ei[0], ei[0] + E1, E1,
                                          xlr, att[0], nsum, xcat);

    // convs 1..3 in one launch
    {
        EdgeAll P;
        int total_nb = 0;
        for (int c = 1; c < 4; c++) {
            int i = c - 1;
            P.src[i]  = ei[c];
            P.dst[i]  = ei[c] + Ec[c];
            P.att[i]  = att[c];
            P.nsum[i] = nsum + (size_t)c * MAXN * 16;
            P.E[i]    = Ec[c];
            P.cofs[i] = c * 256;
            P.xofs[i] = c * 128;
            P.nb[i]   = (Ec[c] + 7) / 8;
            total_nb += P.nb[i];
        }
        edge_fused_all<<<total_nb, 256>>>(P, xlr, xcat);
    }

    // fuse GEMM with inline normalization: xf = (xcat/nsum + bcat) @ fuse_W + fuse_b
    float* xf = (float*)d_out;
    gemm_fuse<<<(N + 127) / 128, 256>>>(xcat, nsum, bcat, fuse_W, fuse_b, xf, N);

    // edge MLP -> output section 1 (persistent, tensor-core batch matvec)
    float* eout = (float*)d_out + (size_t)N * 128;
    edge_mlp<<<148, 512, MLP_SMEM>>>(ei[0], ei[0] + E1, E1, xf, ln_g, ln_b,
                                     mlp_W, mlp_b, edge_attr, eout);

    // dual gather -> output section 2
    float* dout = eout + (size_t)E1 * 128;
    dual_gather<<<(M_oe * 32 + 255) / 256, 256>>>(oemap, M_oe, E1, eout, dout);
}